// round 9
// baseline (speedup 1.0000x reference)
#include <cuda_runtime.h>
#include <cuda_bf16.h>
#include <math.h>
#include <stdint.h>

// ---------------- constants ----------------
#define BATCH 4
#define SEQ   2048
#define EMB   2048
#define NHEAD 16
#define HDIM  128
#define MROWS (BATCH*SEQ)               // 8192
#define ELEMS ((size_t)BATCH*SEQ*EMB)   // 16777216
#define L2E   1.4426950408889634f
#define RMS_EPS 1.1920929e-07f

// ---------------- scratch (device globals: allocation-free) ----------------
__device__ float g_q[ELEMS];
__device__ float g_k[ELEMS];
__device__ __nv_bfloat16 g_ahi[ELEMS];
__device__ __nv_bfloat16 g_alo[ELEMS];
__device__ __nv_bfloat16 g_wthi[(size_t)4*EMB*EMB];
__device__ __nv_bfloat16 g_wtlo[(size_t)4*EMB*EMB];
__device__ __nv_bfloat16 g_qh[ELEMS];
__device__ __nv_bfloat16 g_ql[ELEMS];
__device__ __nv_bfloat16 g_kh[ELEMS];
__device__ __nv_bfloat16 g_kl[ELEMS];
__device__ __nv_bfloat16 g_vh[ELEMS];
__device__ __nv_bfloat16 g_vl[ELEMS];
__device__ float g_cos[SEQ*64];
__device__ float g_sin[SEQ*64];

// =====================================================================
// PTX helpers (standard sm_80+ instructions; valid on plain sm_103)
// =====================================================================
__device__ __forceinline__ uint32_t smem_to_u32(const void* p) {
    uint32_t a;
    asm("{ .reg .u64 t; cvta.to.shared.u64 t, %1; cvt.u32.u64 %0, t; }"
        : "=r"(a) : "l"(p));
    return a;
}

__device__ __forceinline__ void ldsm4(uint32_t* r, uint32_t addr) {
    asm volatile("ldmatrix.sync.aligned.m8n8.x4.shared.b16 {%0,%1,%2,%3}, [%4];"
        : "=r"(r[0]), "=r"(r[1]), "=r"(r[2]), "=r"(r[3]) : "r"(addr));
}
__device__ __forceinline__ void ldsm4t(uint32_t* r, uint32_t addr) {
    asm volatile("ldmatrix.sync.aligned.m8n8.x4.trans.shared.b16 {%0,%1,%2,%3}, [%4];"
        : "=r"(r[0]), "=r"(r[1]), "=r"(r[2]), "=r"(r[3]) : "r"(addr));
}

__device__ __forceinline__ void mma_bf16(float* c, const uint32_t* a, const uint32_t* b) {
    asm volatile(
        "mma.sync.aligned.m16n8k16.row.col.f32.bf16.bf16.f32 "
        "{%0,%1,%2,%3}, {%4,%5,%6,%7}, {%8,%9}, {%0,%1,%2,%3};"
        : "+f"(c[0]), "+f"(c[1]), "+f"(c[2]), "+f"(c[3])
        : "r"(a[0]), "r"(a[1]), "r"(a[2]), "r"(a[3]), "r"(b[0]), "r"(b[1]));
}

__device__ __forceinline__ uint32_t pack_bf16x2(float lo, float hi) {
    uint32_t r;
    asm("cvt.rn.bf16x2.f32 %0, %1, %2;" : "=r"(r) : "f"(hi), "f"(lo));
    return r;
}

// fast exp2 (single SASS MUFU.EX2)
__device__ __forceinline__ float ex2(float x) {
    float y;
    asm("ex2.approx.f32 %0, %1;" : "=f"(y) : "f"(x));
    return y;
}

#define CP_ASYNC16(dst, src) \
    asm volatile("cp.async.cg.shared.global [%0], [%1], 16;" :: "r"(dst), "l"(src) : "memory")
#define CP_COMMIT() asm volatile("cp.async.commit_group;" ::: "memory")
#define CP_WAIT1()  asm volatile("cp.async.wait_group 1;" ::: "memory")
#define CP_WAIT0()  asm volatile("cp.async.wait_group 0;" ::: "memory")

// =====================================================================
// split: fp32 -> bf16 hi + bf16 lo (residual)
// =====================================================================
__global__ __launch_bounds__(256) void split_kernel(
    const float* __restrict__ in,
    __nv_bfloat16* __restrict__ hi, __nv_bfloat16* __restrict__ lo, int n4)
{
    int i = blockIdx.x * 256 + threadIdx.x;
    if (i >= n4) return;
    float4 v = ((const float4*)in)[i];
    __nv_bfloat16 h0 = __float2bfloat16(v.x);
    __nv_bfloat16 h1 = __float2bfloat16(v.y);
    __nv_bfloat16 h2 = __float2bfloat16(v.z);
    __nv_bfloat16 h3 = __float2bfloat16(v.w);
    __nv_bfloat16 l0 = __float2bfloat16(v.x - __bfloat162float(h0));
    __nv_bfloat16 l1 = __float2bfloat16(v.y - __bfloat162float(h1));
    __nv_bfloat16 l2 = __float2bfloat16(v.z - __bfloat162float(h2));
    __nv_bfloat16 l3 = __float2bfloat16(v.w - __bfloat162float(h3));
    __nv_bfloat162* hp = (__nv_bfloat162*)(hi + 4 * (size_t)i);
    __nv_bfloat162* lp = (__nv_bfloat162*)(lo + 4 * (size_t)i);
    hp[0] = __nv_bfloat162(h0, h1); hp[1] = __nv_bfloat162(h2, h3);
    lp[0] = __nv_bfloat162(l0, l1); lp[1] = __nv_bfloat162(l2, l3);
}

// =====================================================================
// 4 weights at once: transpose + split, blockIdx.z selects the weight
// =====================================================================
__global__ __launch_bounds__(256) void wsplit4_kernel(
    const float* __restrict__ w0, const float* __restrict__ w1,
    const float* __restrict__ w2, const float* __restrict__ w3,
    __nv_bfloat16* __restrict__ hi_base, __nv_bfloat16* __restrict__ lo_base)
{
    __shared__ float tile[32][33];
    const int z = blockIdx.z;
    const float* w = (z == 0) ? w0 : (z == 1) ? w1 : (z == 2) ? w2 : w3;
    __nv_bfloat16* hi = hi_base + (size_t)z * EMB * EMB;
    __nv_bfloat16* lo = lo_base + (size_t)z * EMB * EMB;

    int n0 = blockIdx.x * 32, k0 = blockIdx.y * 32;
    int tx = threadIdx.x & 31, ty = threadIdx.x >> 5;
#pragma unroll
    for (int i = 0; i < 32; i += 8)
        tile[ty + i][tx] = w[(size_t)(k0 + ty + i) * EMB + n0 + tx];
    __syncthreads();
#pragma unroll
    for (int i = 0; i < 32; i += 8) {
        float v = tile[tx][ty + i];
        __nv_bfloat16 h = __float2bfloat16(v);
        size_t o = (size_t)(n0 + ty + i) * EMB + k0 + tx;
        hi[o] = h;
        lo[o] = __float2bfloat16(v - __bfloat162float(h));
    }
}

// =====================================================================
// RoPE table precompute (double precision, once)
// =====================================================================
__global__ __launch_bounds__(256) void rope_table_kernel(
    float* __restrict__ ct, float* __restrict__ st)
{
    const int idx = blockIdx.x * 256 + threadIdx.x;
    if (idx >= SEQ * 64) return;
    const int tp = idx >> 6, i = idx & 63;
    double inv = exp(-((double)i / 64.0) * log(10000.0));
    double ang = (double)tp * inv;
    double sd, cd;
    sincos(ang, &sd, &cd);
    ct[idx] = (float)cd;
    st[idx] = (float)sd;
}

// =====================================================================
// mma.sync GEMM: C = A * B^T, split bf16 3-chain, 2-stage cp.async.
// Block tile 256x128x64, 512 threads (16 warps, 4m x 4n), warp tile 64x32.
// mode 0: write fp32 to c0 (row stride EMB).
// mode 1: QKV fused (N=6144): n<2048 -> c0 fp32, <4096 -> c1 fp32,
//         else V written directly as bf16 hi/lo (c2h/c2l).
// =====================================================================
#define BM 256
#define BN 128
#define BK 64
#define RSTRB 144
#define TA (256 * RSTRB)          // 36864 (A tile: 256 rows)
#define TB (128 * RSTRB)          // 18432 (B tile: 128 rows)
#define STG_B (2*TA + 2*TB)       // 110592
#define GEMM_SMEM (2 * STG_B)     // 221184

__global__ __launch_bounds__(512) void mma_gemm_kernel(
    const __nv_bfloat16* __restrict__ Ahi, const __nv_bfloat16* __restrict__ Alo,
    const __nv_bfloat16* __restrict__ Bhi, const __nv_bfloat16* __restrict__ Blo,
    int K, int mode,
    float* __restrict__ c0, float* __restrict__ c1,
    __nv_bfloat16* __restrict__ c2h, __nv_bfloat16* __restrict__ c2l)
{
    extern __shared__ char smc[];
    const uint32_t sb = smem_to_u32(smc);
    const int t = threadIdx.x;
    const int lane = t & 31;
    const int wid = t >> 5;
    const int warp_m = wid & 3;      // 0..3
    const int warp_n = wid >> 2;     // 0..3
    const int row0 = blockIdx.y * BM;
    const int col0 = blockIdx.x * BN;

    float acc[4][4][4];
#pragma unroll
    for (int i = 0; i < 4; i++)
#pragma unroll
        for (int j = 0; j < 4; j++)
#pragma unroll
            for (int r = 0; r < 4; r++) acc[i][j][r] = 0.f;

    auto load_stage = [&](int s, int k0) {
        const uint32_t base = sb + s * STG_B;
        // A hi/lo: 256 rows x 8 chunks = 2048 copies each
#pragma unroll
        for (int i = 0; i < 4; i++) {
            const int idx = t + i * 512;
            const int r = idx >> 3, c = idx & 7;
            const size_t g = (size_t)(row0 + r) * K + k0 + c * 8;
            const uint32_t d = base + r * RSTRB + c * 16;
            CP_ASYNC16(d, Ahi + g);
            CP_ASYNC16(d + TA, Alo + g);
        }
        // B hi/lo: 128 rows x 8 chunks = 1024 copies each
#pragma unroll
        for (int i = 0; i < 2; i++) {
            const int idx = t + i * 512;
            const int r = idx >> 3, c = idx & 7;
            const size_t g = (size_t)(col0 + r) * K + k0 + c * 8;
            const uint32_t d = base + 2 * TA + r * RSTRB + c * 16;
            CP_ASYNC16(d, Bhi + g);
            CP_ASYNC16(d + TB, Blo + g);
        }
    };

    const int nIter = K / BK;
    load_stage(0, 0);
    CP_COMMIT();

    for (int it = 0; it < nIter; it++) {
        if (it + 1 < nIter) {
            load_stage((it + 1) & 1, (it + 1) * BK);
            CP_COMMIT();
            CP_WAIT1();
        } else {
            CP_WAIT0();
        }
        __syncthreads();

        const uint32_t abase = sb + (it & 1) * STG_B;
        const uint32_t bbase = abase + 2 * TA;
        const int arow = warp_m * 64 + (lane & 15);
        const int brow = warp_n * 32 + ((lane >> 4) << 3) + (lane & 7);

#pragma unroll
        for (int ks = 0; ks < 4; ks++) {
            uint32_t ah[4][4], al[4][4], bh[2][4], bl[2][4];
            const uint32_t acol = ks * 32 + ((lane >> 4) << 4);
            const uint32_t bcol = ks * 32 + (((lane >> 3) & 1) << 4);
#pragma unroll
            for (int mf = 0; mf < 4; mf++) {
                const uint32_t ad = abase + (arow + mf * 16) * RSTRB + acol;
                ldsm4(ah[mf], ad);
                ldsm4(al[mf], ad + TA);
            }
#pragma unroll
            for (int np = 0; np < 2; np++) {
                const uint32_t bd = bbase + (brow + np * 16) * RSTRB + bcol;
                ldsm4(bh[np], bd);
                ldsm4(bl[np], bd + TB);
            }
#pragma unroll
            for (int mf = 0; mf < 4; mf++) {
#pragma unroll
                for (int nf = 0; nf < 4; nf++) {
                    const uint32_t* bhp = &bh[nf >> 1][(nf & 1) * 2];
                    const uint32_t* blp = &bl[nf >> 1][(nf & 1) * 2];
                    mma_bf16(acc[mf][nf], ah[mf], bhp);
                    mma_bf16(acc[mf][nf], ah[mf], blp);
                    mma_bf16(acc[mf][nf], al[mf], bhp);
                }
            }
        }
        __syncthreads();
    }

    // ---- epilogue ----
    const int mbase = row0 + warp_m * 64 + (lane >> 2);
    const int nb = col0 + warp_n * 32 + (lane & 3) * 2;
#pragma unroll
    for (int mf = 0; mf < 4; mf++) {
#pragma unroll
        for (int nf = 0; nf < 4; nf++) {
            const int n = nb + nf * 8;
            const int m0 = mbase + mf * 16;
            const float* a = acc[mf][nf];
            if (mode == 0) {
                const size_t o0 = (size_t)m0 * EMB + n;
                *(float2*)(c0 + o0) = make_float2(a[0], a[1]);
                *(float2*)(c0 + o0 + 8 * EMB) = make_float2(a[2], a[3]);
            } else {
                const int which = n >> 11;
                const int nloc = n & 2047;
                const size_t o0 = (size_t)m0 * EMB + nloc;
                if (which == 0) {
                    *(float2*)(c0 + o0) = make_float2(a[0], a[1]);
                    *(float2*)(c0 + o0 + 8 * EMB) = make_float2(a[2], a[3]);
                } else if (which == 1) {
                    *(float2*)(c1 + o0) = make_float2(a[0], a[1]);
                    *(float2*)(c1 + o0 + 8 * EMB) = make_float2(a[2], a[3]);
                } else {
                    uint32_t h0 = pack_bf16x2(a[0], a[1]);
                    uint32_t h1 = pack_bf16x2(a[2], a[3]);
                    uint32_t l0 = pack_bf16x2(a[0] - __uint_as_float(h0 << 16),
                                              a[1] - __uint_as_float(h0 & 0xffff0000u));
                    uint32_t l1 = pack_bf16x2(a[2] - __uint_as_float(h1 << 16),
                                              a[3] - __uint_as_float(h1 & 0xffff0000u));
                    *(uint32_t*)(c2h + o0) = h0;
                    *(uint32_t*)(c2h + o0 + 8 * EMB) = h1;
                    *(uint32_t*)(c2l + o0) = l0;
                    *(uint32_t*)(c2l + o0 + 8 * EMB) = l1;
                }
            }
        }
    }
}

// =====================================================================
// RoPE + RMSNorm + scale + bf16 hi/lo split (table-based, pure fp32)
// =====================================================================
__global__ void ropeprep_kernel(const float* __restrict__ buf,
                                const float* __restrict__ ct,
                                const float* __restrict__ st,
                                __nv_bfloat16* __restrict__ hi,
                                __nv_bfloat16* __restrict__ lo,
                                float outscale)
{
    const int h = blockIdx.x, tp = blockIdx.y, b = blockIdx.z;
    const int i = threadIdx.x;  // 0..63
    const size_t base = ((size_t)b * SEQ + tp) * EMB + (size_t)h * HDIM;

    float x1 = buf[base + i];
    float x2 = buf[base + 64 + i];

    const float c = ct[tp * 64 + i];
    const float s = st[tp * 64 + i];

    float n1 = x1 * c - x2 * s;
    float n2 = x1 * s + x2 * c;

    float sq = n1 * n1 + n2 * n2;
#pragma unroll
    for (int o = 16; o > 0; o >>= 1)
        sq += __shfl_xor_sync(0xffffffffu, sq, o);

    __shared__ float partial[2];
    if ((i & 31) == 0) partial[i >> 5] = sq;
    __syncthreads();
    float tot = partial[0] + partial[1];
    float r = rsqrtf(tot * (1.0f / 128.0f) + RMS_EPS) * outscale;

    float y1 = n1 * r, y2 = n2 * r;
    __nv_bfloat16 h1 = __float2bfloat16(y1);
    __nv_bfloat16 h2 = __float2bfloat16(y2);
    hi[base + i]      = h1;
    hi[base + 64 + i] = h2;
    lo[base + i]      = __float2bfloat16(y1 - __bfloat162float(h1));
    lo[base + 64 + i] = __float2bfloat16(y2 - __bfloat162float(h2));
}

// =====================================================================
// Flash attention on mma.sync bf16 (split hi/lo, 3 chains both GEMMs).
// Output written directly as bf16 hi/lo for the WO GEMM.
// =====================================================================
#define FL_STR  136
#define FL_ROWB (FL_STR*2)
#define FL_TILE (64*FL_ROWB)
#define FL_STG  (4*FL_TILE)
#define FL_QLO  (128*FL_ROWB)
#define FL_SMEM (3*FL_STG)

__global__ __launch_bounds__(256, 1) void flash_mma_kernel(
    const __nv_bfloat16* __restrict__ Qh, const __nv_bfloat16* __restrict__ Ql,
    const __nv_bfloat16* __restrict__ Kh, const __nv_bfloat16* __restrict__ Kl,
    const __nv_bfloat16* __restrict__ Vh, const __nv_bfloat16* __restrict__ Vl,
    __nv_bfloat16* __restrict__ Yh, __nv_bfloat16* __restrict__ Yl)
{
    extern __shared__ char smc[];
    const uint32_t sb = smem_to_u32(smc);
    const int t = threadIdx.x;
    const int lane = t & 31;
    const int w = t >> 5;
    const int qi = gridDim.x - 1 - blockIdx.x;
    const int h = blockIdx.y, b = blockIdx.z;
    const int qs = qi * 128;
    const size_t hb = ((size_t)b * SEQ) * EMB + (size_t)h * HDIM;

#pragma unroll
    for (int i = 0; i < 8; i++) {
        const int idx = t + i * 256;
        const int r = idx >> 4, c = idx & 15;
        const size_t g = hb + (size_t)(qs + r) * EMB + c * 8;
        CP_ASYNC16(sb + r * FL_ROWB + c * 16, Qh + g);
        CP_ASYNC16(sb + FL_QLO + r * FL_ROWB + c * 16, Ql + g);
    }
    CP_COMMIT();

    auto load_kv = [&](int s, int ks) {
        const uint32_t base = sb + FL_STG * (1 + s);
        const __nv_bfloat16* srcs[4] = {Kh, Kl, Vh, Vl};
#pragma unroll
        for (int tile = 0; tile < 4; tile++) {
#pragma unroll
            for (int i = 0; i < 4; i++) {
                const int idx = t + i * 256;
                const int r = idx >> 4, c = idx & 15;
                CP_ASYNC16(base + tile * FL_TILE + r * FL_ROWB + c * 16,
                           srcs[tile] + hb + (size_t)(ks + r) * EMB + c * 8);
            }
        }
    };

    load_kv(0, 0);
    CP_COMMIT();

    float m0 = -INFINITY, m1 = -INFINITY, l0 = 0.f, l1 = 0.f;
    float o[16][4];
#pragma unroll
    for (int i = 0; i < 16; i++)
#pragma unroll
        for (int j = 0; j < 4; j++) o[i][j] = 0.f;

    const uint32_t q_addr = sb + (w * 16 + (lane & 15)) * FL_ROWB + (lane >> 4) * 16;
    const int krow = (lane & 7) + ((lane >> 4) << 3);
    const uint32_t kcolb = ((lane >> 3) & 1) * 16;
    const int vrow = (lane & 7) + (((lane >> 3) & 1) << 3);
    const uint32_t vcolb = (lane >> 4) * 16;

    const int r0g = qs + w * 16 + (lane >> 2);
    const int r1g = r0g + 8;
    const int nkt = (qs + 128) / 64;

    for (int jt = 0; jt < nkt; jt++) {
        CP_WAIT0();
        __syncthreads();
        if (jt + 1 < nkt) { load_kv((jt + 1) & 1, (jt + 1) * 64); CP_COMMIT(); }

        const int ks = jt * 64;
        if (ks <= qs + w * 16 + 15) {
            const uint32_t kb = sb + FL_STG * (1 + (jt & 1));

            float s[8][4];
#pragma unroll
            for (int i = 0; i < 8; i++)
#pragma unroll
                for (int j = 0; j < 4; j++) s[i][j] = 0.f;

#pragma unroll
            for (int kf = 0; kf < 8; kf++) {
                uint32_t qa[4], qla[4];
                ldsm4(qa, q_addr + kf * 32);
                ldsm4(qla, q_addr + FL_QLO + kf * 32);
#pragma unroll
                for (int nfp = 0; nfp < 4; nfp++) {
                    uint32_t kh4[4], kl4[4];
                    const uint32_t ka = kb + (nfp * 16 + krow) * FL_ROWB + kcolb + kf * 32;
                    ldsm4(kh4, ka);
                    ldsm4(kl4, ka + FL_TILE);
                    mma_bf16(s[2 * nfp], qa, kh4);
                    mma_bf16(s[2 * nfp], qa, kl4);
                    mma_bf16(s[2 * nfp], qla, kh4);
                    mma_bf16(s[2 * nfp + 1], qa, kh4 + 2);
                    mma_bf16(s[2 * nfp + 1], qa, kl4 + 2);
                    mma_bf16(s[2 * nfp + 1], qla, kh4 + 2);
                }
            }

            if (ks + 63 > r0g) {
#pragma unroll
                for (int nf = 0; nf < 8; nf++) {
                    const int kc = ks + nf * 8 + (lane & 3) * 2;
                    if (kc > r0g)     s[nf][0] = -1e30f;
                    if (kc + 1 > r0g) s[nf][1] = -1e30f;
                    if (kc > r1g)     s[nf][2] = -1e30f;
                    if (kc + 1 > r1g) s[nf][3] = -1e30f;
                }
            }

            float m0l = -INFINITY, m1l = -INFINITY;
#pragma unroll
            for (int nf = 0; nf < 8; nf++) {
                m0l = fmaxf(m0l, fmaxf(s[nf][0], s[nf][1]));
                m1l = fmaxf(m1l, fmaxf(s[nf][2], s[nf][3]));
            }
            m0l = fmaxf(m0l, __shfl_xor_sync(0xffffffffu, m0l, 1));
            m0l = fmaxf(m0l, __shfl_xor_sync(0xffffffffu, m0l, 2));
            m1l = fmaxf(m1l, __shfl_xor_sync(0xffffffffu, m1l, 1));
            m1l = fmaxf(m1l, __shfl_xor_sync(0xffffffffu, m1l, 2));
            const float m0n = fmaxf(m0, m0l), m1n = fmaxf(m1, m1l);
            const float a0 = ex2((m0 - m0n) * L2E);
            const float a1 = ex2((m1 - m1n) * L2E);
            m0 = m0n; m1 = m1n;

            float sum0 = 0.f, sum1 = 0.f;
#pragma unroll
            for (int nf = 0; nf < 8; nf++) {
                s[nf][0] = ex2((s[nf][0] - m0n) * L2E); sum0 += s[nf][0];
                s[nf][1] = ex2((s[nf][1] - m0n) * L2E); sum0 += s[nf][1];
                s[nf][2] = ex2((s[nf][2] - m1n) * L2E); sum1 += s[nf][2];
                s[nf][3] = ex2((s[nf][3] - m1n) * L2E); sum1 += s[nf][3];
            }
            sum0 += __shfl_xor_sync(0xffffffffu, sum0, 1);
            sum0 += __shfl_xor_sync(0xffffffffu, sum0, 2);
            sum1 += __shfl_xor_sync(0xffffffffu, sum1, 1);
            sum1 += __shfl_xor_sync(0xffffffffu, sum1, 2);
            l0 = l0 * a0 + sum0;
            l1 = l1 * a1 + sum1;

#pragma unroll
            for (int nf = 0; nf < 16; nf++) {
                o[nf][0] *= a0; o[nf][1] *= a0;
                o[nf][2] *= a1; o[nf][3] *= a1;
            }

            const uint32_t vb = kb + 2 * FL_TILE;
#pragma unroll
            for (int kf2 = 0; kf2 < 4; kf2++) {
                uint32_t ah[4], al[4];
#pragma unroll
                for (int q2 = 0; q2 < 2; q2++) {
                    const float* sp = s[2 * kf2 + q2];
#pragma unroll
                    for (int rr = 0; rr < 2; rr++) {
                        const float pe = sp[rr * 2], po = sp[rr * 2 + 1];
                        const uint32_t ph = pack_bf16x2(pe, po);
                        const float rle = pe - __uint_as_float(ph << 16);
                        const float rlo = po - __uint_as_float(ph & 0xffff0000u);
                        ah[q2 * 2 + rr] = ph;
                        al[q2 * 2 + rr] = pack_bf16x2(rle, rlo);
                    }
                }
#pragma unroll
                for (int nfp = 0; nfp < 8; nfp++) {
                    uint32_t vh4[4], vl4[4];
                    const uint32_t va = vb + (kf2 * 16 + vrow) * FL_ROWB + vcolb + nfp * 32;
                    ldsm4t(vh4, va);
                    ldsm4t(vl4, va + FL_TILE);
                    mma_bf16(o[2 * nfp], ah, vh4);
                    mma_bf16(o[2 * nfp], ah, vl4);
                    mma_bf16(o[2 * nfp], al, vh4);
                    mma_bf16(o[2 * nfp + 1], ah, vh4 + 2);
                    mma_bf16(o[2 * nfp + 1], ah, vl4 + 2);
                    mma_bf16(o[2 * nfp + 1], al, vh4 + 2);
                }
            }
        }
    }

    const float il0 = 1.f / l0, il1 = 1.f / l1;
    const size_t yb = hb + (size_t)r0g * EMB + (lane & 3) * 2;
#pragma unroll
    for (int nf = 0; nf < 16; nf++) {
        const float a0v = o[nf][0] * il0, a1v = o[nf][1] * il0;
        const float b0v = o[nf][2] * il1, b1v = o[nf][3] * il1;
        const uint32_t h0 = pack_bf16x2(a0v, a1v);
        const uint32_t h1 = pack_bf16x2(b0v, b1v);
        const uint32_t q0 = pack_bf16x2(a0v - __uint_as_float(h0 << 16),
                                        a1v - __uint_as_float(h0 & 0xffff0000u));
        const uint32_t q1 = pack_bf16x2(b0v - __uint_as_float(h1 << 16),
                                        b1v - __uint_as_float(h1 & 0xffff0000u));
        *(uint32_t*)(Yh + yb + nf * 8) = h0;
        *(uint32_t*)(Yl + yb + nf * 8) = q0;
        *(uint32_t*)(Yh + yb + (size_t)8 * EMB + nf * 8) = h1;
        *(uint32_t*)(Yl + yb + (size_t)8 * EMB + nf * 8) = q1;
    }
}

// =====================================================================
// launch
// =====================================================================
extern "C" void kernel_launch(void* const* d_in, const int* in_sizes, int n_in,
                              void* d_out, int out_size)
{
    const float* x  = (const float*)d_in[0];
    const float* wq = (const float*)d_in[1];
    const float* wk = (const float*)d_in[2];
    const float* wv = (const float*)d_in[3];
    const float* wo = (const float*)d_in[4];
    float* out = (float*)d_out;

    float *gq, *gk, *ct, *st;
    __nv_bfloat16 *ahi, *alo, *wthi, *wtlo, *qh, *ql, *kh, *kl, *vh, *vl;
    cudaGetSymbolAddress((void**)&gq, g_q);
    cudaGetSymbolAddress((void**)&gk, g_k);
    cudaGetSymbolAddress((void**)&ct, g_cos);
    cudaGetSymbolAddress((void**)&st, g_sin);
    cudaGetSymbolAddress((void**)&ahi, g_ahi);
    cudaGetSymbolAddress((void**)&alo, g_alo);
    cudaGetSymbolAddress((void**)&wthi, g_wthi);
    cudaGetSymbolAddress((void**)&wtlo, g_wtlo);
    cudaGetSymbolAddress((void**)&qh, g_qh);
    cudaGetSymbolAddress((void**)&ql, g_ql);
    cudaGetSymbolAddress((void**)&kh, g_kh);
    cudaGetSymbolAddress((void**)&kl, g_kl);
    cudaGetSymbolAddress((void**)&vh, g_vh);
    cudaGetSymbolAddress((void**)&vl, g_vl);

    cudaFuncSetAttribute(mma_gemm_kernel,
                         cudaFuncAttributeMaxDynamicSharedMemorySize, GEMM_SMEM);
    cudaFuncSetAttribute(flash_mma_kernel,
                         cudaFuncAttributeMaxDynamicSharedMemorySize, FL_SMEM);

    const int n4 = (int)(ELEMS / 4);
    const dim3 sgrid((n4 + 255) / 256);
    const size_t WSZ = (size_t)EMB * EMB;

    // prep: rope tables, split x, all 4 weights in one launch
    rope_table_kernel<<<(SEQ * 64 + 255) / 256, 256>>>(ct, st);
    split_kernel<<<sgrid, 256>>>(x, ahi, alo, n4);
    dim3 wgrid(EMB / 32, EMB / 32, 4);
    wsplit4_kernel<<<wgrid, 256>>>(wq, wk, wv, wo, wthi, wtlo);

    // fused QKV GEMM: q,k fp32; v directly bf16 hi/lo
    dim3 qkvgrid(3 * EMB / BN, MROWS / BM);   // (48, 32)
    mma_gemm_kernel<<<qkvgrid, 512, GEMM_SMEM>>>(
        ahi, alo, wthi, wtlo, EMB, 1, gq, gk, vh, vl);

    // RoPE + RMSNorm + split (scale folded into Q)
    dim3 rgrid(NHEAD, SEQ, BATCH);
    ropeprep_kernel<<<rgrid, 64>>>(gq, ct, st, qh, ql, 0.08838834764831845f);
    ropeprep_kernel<<<rgrid, 64>>>(gk, ct, st, kh, kl, 1.0f);

    // flash attention -> writes ahi/alo (bf16 hi/lo) directly
    dim3 fgrid(SEQ / 128, NHEAD, BATCH);
    flash_mma_kernel<<<fgrid, 256, FL_SMEM>>>(qh, ql, kh, kl, vh, vl, ahi, alo);

    // out = y @ wo
    dim3 ogrid(EMB / BN, MROWS / BM);         // (16, 32)
    mma_gemm_kernel<<<ogrid, 512, GEMM_SMEM>>>(
        ahi, alo, wthi + 3 * WSZ, wtlo + 3 * WSZ, EMB, 0,
        out, nullptr, nullptr, nullptr);
}

// round 10
// speedup vs baseline: 1.0607x; 1.0607x over previous
#include <cuda_runtime.h>
#include <cuda_bf16.h>
#include <math.h>
#include <stdint.h>

// ---------------- constants ----------------
#define BATCH 4
#define SEQ   2048
#define EMB   2048
#define NHEAD 16
#define HDIM  128
#define MROWS (BATCH*SEQ)               // 8192
#define ELEMS ((size_t)BATCH*SEQ*EMB)   // 16777216
#define L2E   1.4426950408889634f
#define RMS_EPS 1.1920929e-07f

// ---------------- scratch (device globals: allocation-free) ----------------
__device__ float g_q[ELEMS];
__device__ float g_k[ELEMS];
__device__ __nv_bfloat16 g_ahi[ELEMS];
__device__ __nv_bfloat16 g_alo[ELEMS];
__device__ __nv_bfloat16 g_wthi[(size_t)4*EMB*EMB];
__device__ __nv_bfloat16 g_wtlo[(size_t)4*EMB*EMB];
__device__ __nv_bfloat16 g_qh[ELEMS];
__device__ __nv_bfloat16 g_ql[ELEMS];
__device__ __nv_bfloat16 g_kh[ELEMS];
__device__ __nv_bfloat16 g_kl[ELEMS];
__device__ __nv_bfloat16 g_vh[ELEMS];
__device__ __nv_bfloat16 g_vl[ELEMS];
__device__ float g_cos[SEQ*64];
__device__ float g_sin[SEQ*64];

// =====================================================================
// PTX helpers (standard sm_80+ instructions; valid on plain sm_103)
// =====================================================================
__device__ __forceinline__ uint32_t smem_to_u32(const void* p) {
    uint32_t a;
    asm("{ .reg .u64 t; cvta.to.shared.u64 t, %1; cvt.u32.u64 %0, t; }"
        : "=r"(a) : "l"(p));
    return a;
}

__device__ __forceinline__ void ldsm4(uint32_t* r, uint32_t addr) {
    asm volatile("ldmatrix.sync.aligned.m8n8.x4.shared.b16 {%0,%1,%2,%3}, [%4];"
        : "=r"(r[0]), "=r"(r[1]), "=r"(r[2]), "=r"(r[3]) : "r"(addr));
}
__device__ __forceinline__ void ldsm4t(uint32_t* r, uint32_t addr) {
    asm volatile("ldmatrix.sync.aligned.m8n8.x4.trans.shared.b16 {%0,%1,%2,%3}, [%4];"
        : "=r"(r[0]), "=r"(r[1]), "=r"(r[2]), "=r"(r[3]) : "r"(addr));
}

__device__ __forceinline__ void mma_bf16(float* c, const uint32_t* a, const uint32_t* b) {
    asm volatile(
        "mma.sync.aligned.m16n8k16.row.col.f32.bf16.bf16.f32 "
        "{%0,%1,%2,%3}, {%4,%5,%6,%7}, {%8,%9}, {%0,%1,%2,%3};"
        : "+f"(c[0]), "+f"(c[1]), "+f"(c[2]), "+f"(c[3])
        : "r"(a[0]), "r"(a[1]), "r"(a[2]), "r"(a[3]), "r"(b[0]), "r"(b[1]));
}

__device__ __forceinline__ uint32_t pack_bf16x2(float lo, float hi) {
    uint32_t r;
    asm("cvt.rn.bf16x2.f32 %0, %1, %2;" : "=r"(r) : "f"(hi), "f"(lo));
    return r;
}

// fast exp2 (single SASS MUFU.EX2)
__device__ __forceinline__ float ex2(float x) {
    float y;
    asm("ex2.approx.f32 %0, %1;" : "=f"(y) : "f"(x));
    return y;
}

#define CP_ASYNC16(dst, src) \
    asm volatile("cp.async.cg.shared.global [%0], [%1], 16;" :: "r"(dst), "l"(src) : "memory")
#define CP_COMMIT() asm volatile("cp.async.commit_group;" ::: "memory")
#define CP_WAIT0()  asm volatile("cp.async.wait_group 0;" ::: "memory")

// =====================================================================
// split: fp32 -> bf16 hi + bf16 lo (residual)
// =====================================================================
__global__ __launch_bounds__(256) void split_kernel(
    const float* __restrict__ in,
    __nv_bfloat16* __restrict__ hi, __nv_bfloat16* __restrict__ lo, int n4)
{
    int i = blockIdx.x * 256 + threadIdx.x;
    if (i >= n4) return;
    float4 v = ((const float4*)in)[i];
    __nv_bfloat16 h0 = __float2bfloat16(v.x);
    __nv_bfloat16 h1 = __float2bfloat16(v.y);
    __nv_bfloat16 h2 = __float2bfloat16(v.z);
    __nv_bfloat16 h3 = __float2bfloat16(v.w);
    __nv_bfloat16 l0 = __float2bfloat16(v.x - __bfloat162float(h0));
    __nv_bfloat16 l1 = __float2bfloat16(v.y - __bfloat162float(h1));
    __nv_bfloat16 l2 = __float2bfloat16(v.z - __bfloat162float(h2));
    __nv_bfloat16 l3 = __float2bfloat16(v.w - __bfloat162float(h3));
    __nv_bfloat162* hp = (__nv_bfloat162*)(hi + 4 * (size_t)i);
    __nv_bfloat162* lp = (__nv_bfloat162*)(lo + 4 * (size_t)i);
    hp[0] = __nv_bfloat162(h0, h1); hp[1] = __nv_bfloat162(h2, h3);
    lp[0] = __nv_bfloat162(l0, l1); lp[1] = __nv_bfloat162(l2, l3);
}

// =====================================================================
// 4 weights at once: transpose + split, blockIdx.z selects the weight
// =====================================================================
__global__ __launch_bounds__(256) void wsplit4_kernel(
    const float* __restrict__ w0, const float* __restrict__ w1,
    const float* __restrict__ w2, const float* __restrict__ w3,
    __nv_bfloat16* __restrict__ hi_base, __nv_bfloat16* __restrict__ lo_base)
{
    __shared__ float tile[32][33];
    const int z = blockIdx.z;
    const float* w = (z == 0) ? w0 : (z == 1) ? w1 : (z == 2) ? w2 : w3;
    __nv_bfloat16* hi = hi_base + (size_t)z * EMB * EMB;
    __nv_bfloat16* lo = lo_base + (size_t)z * EMB * EMB;

    int n0 = blockIdx.x * 32, k0 = blockIdx.y * 32;
    int tx = threadIdx.x & 31, ty = threadIdx.x >> 5;
#pragma unroll
    for (int i = 0; i < 32; i += 8)
        tile[ty + i][tx] = w[(size_t)(k0 + ty + i) * EMB + n0 + tx];
    __syncthreads();
#pragma unroll
    for (int i = 0; i < 32; i += 8) {
        float v = tile[tx][ty + i];
        __nv_bfloat16 h = __float2bfloat16(v);
        size_t o = (size_t)(n0 + ty + i) * EMB + k0 + tx;
        hi[o] = h;
        lo[o] = __float2bfloat16(v - __bfloat162float(h));
    }
}

// =====================================================================
// RoPE table precompute (double precision, once)
// =====================================================================
__global__ __launch_bounds__(256) void rope_table_kernel(
    float* __restrict__ ct, float* __restrict__ st)
{
    const int idx = blockIdx.x * 256 + threadIdx.x;
    if (idx >= SEQ * 64) return;
    const int tp = idx >> 6, i = idx & 63;
    double inv = exp(-((double)i / 64.0) * log(10000.0));
    double ang = (double)tp * inv;
    double sd, cd;
    sincos(ang, &sd, &cd);
    ct[idx] = (float)cd;
    st[idx] = (float)sd;
}

// =====================================================================
// mma.sync GEMM: C = A * B^T, split bf16 3-chain, 2-stage cp.async,
// ONE __syncthreads per k-iteration.
// Block tile 128x256x64, 8 warps (2 x 4), warp tile 64x64.
// mode 0: write fp32 to c0 (row stride EMB).
// mode 1: QKV fused (N=6144): n<2048 -> c0 fp32, <4096 -> c1 fp32,
//         else V written directly as bf16 hi/lo (c2h/c2l).
// =====================================================================
#define BM 128
#define BN 256
#define BK 64
#define RSTRB 144
#define TA (128 * RSTRB)          // 18432
#define TB (256 * RSTRB)          // 36864
#define STG_B (2*TA + 2*TB)       // 110592
#define GEMM_SMEM (2 * STG_B)     // 221184

__global__ __launch_bounds__(256) void mma_gemm_kernel(
    const __nv_bfloat16* __restrict__ Ahi, const __nv_bfloat16* __restrict__ Alo,
    const __nv_bfloat16* __restrict__ Bhi, const __nv_bfloat16* __restrict__ Blo,
    int K, int mode,
    float* __restrict__ c0, float* __restrict__ c1,
    __nv_bfloat16* __restrict__ c2h, __nv_bfloat16* __restrict__ c2l)
{
    extern __shared__ char smc[];
    const uint32_t sb = smem_to_u32(smc);
    const int t = threadIdx.x;
    const int lane = t & 31;
    const int wid = t >> 5;
    const int warp_m = wid & 1;
    const int warp_n = wid >> 1;
    const int row0 = blockIdx.y * BM;
    const int col0 = blockIdx.x * BN;

    float acc[4][8][4];
#pragma unroll
    for (int i = 0; i < 4; i++)
#pragma unroll
        for (int j = 0; j < 8; j++)
#pragma unroll
            for (int r = 0; r < 4; r++) acc[i][j][r] = 0.f;

    auto load_stage = [&](int s, int k0) {
        const uint32_t base = sb + s * STG_B;
#pragma unroll
        for (int i = 0; i < 4; i++) {
            const int idx = t + i * 256;
            const int r = idx >> 3, c = idx & 7;
            const size_t g = (size_t)(row0 + r) * K + k0 + c * 8;
            const uint32_t d = base + r * RSTRB + c * 16;
            CP_ASYNC16(d, Ahi + g);
            CP_ASYNC16(d + TA, Alo + g);
        }
#pragma unroll
        for (int i = 0; i < 8; i++) {
            const int idx = t + i * 256;
            const int r = idx >> 3, c = idx & 7;
            const size_t g = (size_t)(col0 + r) * K + k0 + c * 8;
            const uint32_t d = base + 2 * TA + r * RSTRB + c * 16;
            CP_ASYNC16(d, Bhi + g);
            CP_ASYNC16(d + TB, Blo + g);
        }
    };

    const int nIter = K / BK;
    load_stage(0, 0);
    CP_COMMIT();

    for (int it = 0; it < nIter; it++) {
        // wait for this iteration's tiles, make them visible to all warps,
        // then kick off the next stage BEFORE computing (single sync/iter).
        CP_WAIT0();
        __syncthreads();
        if (it + 1 < nIter) {
            load_stage((it + 1) & 1, (it + 1) * BK);
            CP_COMMIT();
        }

        const uint32_t abase = sb + (it & 1) * STG_B;
        const uint32_t bbase = abase + 2 * TA;
        const int arow = warp_m * 64 + (lane & 15);
        const int brow = warp_n * 64 + ((lane >> 4) << 3) + (lane & 7);

#pragma unroll
        for (int ks = 0; ks < 4; ks++) {
            uint32_t ah[4][4], al[4][4], bh[4][4], bl[4][4];
            const uint32_t acol = ks * 32 + ((lane >> 4) << 4);
            const uint32_t bcol = ks * 32 + (((lane >> 3) & 1) << 4);
#pragma unroll
            for (int mf = 0; mf < 4; mf++) {
                const uint32_t ad = abase + (arow + mf * 16) * RSTRB + acol;
                ldsm4(ah[mf], ad);
                ldsm4(al[mf], ad + TA);
            }
#pragma unroll
            for (int bf = 0; bf < 4; bf++) {
                const uint32_t bd = bbase + (brow + bf * 16) * RSTRB + bcol;
                ldsm4(bh[bf], bd);
                ldsm4(bl[bf], bd + TB);
            }
#pragma unroll
            for (int mf = 0; mf < 4; mf++) {
#pragma unroll
                for (int nf = 0; nf < 8; nf++) {
                    const uint32_t* bhp = &bh[nf >> 1][(nf & 1) * 2];
                    const uint32_t* blp = &bl[nf >> 1][(nf & 1) * 2];
                    mma_bf16(acc[mf][nf], ah[mf], bhp);
                    mma_bf16(acc[mf][nf], ah[mf], blp);
                    mma_bf16(acc[mf][nf], al[mf], bhp);
                }
            }
        }
    }

    // ---- epilogue ----
    const int mbase = row0 + warp_m * 64 + (lane >> 2);
    const int nb = col0 + warp_n * 64 + (lane & 3) * 2;
#pragma unroll
    for (int mf = 0; mf < 4; mf++) {
#pragma unroll
        for (int nf = 0; nf < 8; nf++) {
            const int n = nb + nf * 8;
            const int m0 = mbase + mf * 16;
            const float* a = acc[mf][nf];
            if (mode == 0) {
                const size_t o0 = (size_t)m0 * EMB + n;
                *(float2*)(c0 + o0) = make_float2(a[0], a[1]);
                *(float2*)(c0 + o0 + 8 * EMB) = make_float2(a[2], a[3]);
            } else {
                const int which = n >> 11;
                const int nloc = n & 2047;
                const size_t o0 = (size_t)m0 * EMB + nloc;
                if (which == 0) {
                    *(float2*)(c0 + o0) = make_float2(a[0], a[1]);
                    *(float2*)(c0 + o0 + 8 * EMB) = make_float2(a[2], a[3]);
                } else if (which == 1) {
                    *(float2*)(c1 + o0) = make_float2(a[0], a[1]);
                    *(float2*)(c1 + o0 + 8 * EMB) = make_float2(a[2], a[3]);
                } else {
                    uint32_t h0 = pack_bf16x2(a[0], a[1]);
                    uint32_t h1 = pack_bf16x2(a[2], a[3]);
                    uint32_t l0 = pack_bf16x2(a[0] - __uint_as_float(h0 << 16),
                                              a[1] - __uint_as_float(h0 & 0xffff0000u));
                    uint32_t l1 = pack_bf16x2(a[2] - __uint_as_float(h1 << 16),
                                              a[3] - __uint_as_float(h1 & 0xffff0000u));
                    *(uint32_t*)(c2h + o0) = h0;
                    *(uint32_t*)(c2h + o0 + 8 * EMB) = h1;
                    *(uint32_t*)(c2l + o0) = l0;
                    *(uint32_t*)(c2l + o0 + 8 * EMB) = l1;
                }
            }
        }
    }
}

// =====================================================================
// RoPE + RMSNorm + scale + bf16 hi/lo split.
// One WARP per (buffer, b, t, h) head-row; Q and K in one launch.
// block = 256 (8 warps); grid.x = 2*BATCH*SEQ*NHEAD/8 = 32768.
// =====================================================================
__global__ __launch_bounds__(256) void ropeprep2_kernel(
    const float* __restrict__ q, const float* __restrict__ k,
    const float* __restrict__ ct, const float* __restrict__ st,
    __nv_bfloat16* __restrict__ qh, __nv_bfloat16* __restrict__ ql,
    __nv_bfloat16* __restrict__ kh, __nv_bfloat16* __restrict__ kl,
    float qscale)
{
    const int w = blockIdx.x * 8 + (threadIdx.x >> 5);
    const int lane = threadIdx.x & 31;
    const int sel = w >> 17;            // 0=Q, 1=K
    const int w2 = w & 131071;
    const int b = w2 >> 15;
    const int r = w2 & 32767;
    const int tp = r >> 4;
    const int h = r & 15;

    const float* buf = sel ? k : q;
    const size_t base = ((size_t)b * SEQ + tp) * EMB + (size_t)h * HDIM;

    // pair indices i0=lane, i1=lane+32 (64 pairs total per head)
    const float x1a = buf[base + lane];
    const float x1b = buf[base + 32 + lane];
    const float x2a = buf[base + 64 + lane];
    const float x2b = buf[base + 96 + lane];
    const float ca = ct[tp * 64 + lane],     sa = st[tp * 64 + lane];
    const float cb = ct[tp * 64 + 32 + lane], sb2 = st[tp * 64 + 32 + lane];

    const float n1a = x1a * ca - x2a * sa;
    const float n2a = x1a * sa + x2a * ca;
    const float n1b = x1b * cb - x2b * sb2;
    const float n2b = x1b * sb2 + x2b * cb;

    float sq = n1a * n1a + n2a * n2a + n1b * n1b + n2b * n2b;
#pragma unroll
    for (int o = 16; o > 0; o >>= 1)
        sq += __shfl_xor_sync(0xffffffffu, sq, o);

    const float osc = sel ? 1.0f : qscale;
    const float rs = rsqrtf(sq * (1.0f / 128.0f) + RMS_EPS) * osc;

    __nv_bfloat16* dh = sel ? kh : qh;
    __nv_bfloat16* dl = sel ? kl : ql;
    const float y0 = n1a * rs, y1 = n1b * rs, y2 = n2a * rs, y3 = n2b * rs;
    __nv_bfloat16 h0 = __float2bfloat16(y0);
    __nv_bfloat16 h1 = __float2bfloat16(y1);
    __nv_bfloat16 h2 = __float2bfloat16(y2);
    __nv_bfloat16 h3 = __float2bfloat16(y3);
    dh[base + lane]      = h0;
    dh[base + 32 + lane] = h1;
    dh[base + 64 + lane] = h2;
    dh[base + 96 + lane] = h3;
    dl[base + lane]      = __float2bfloat16(y0 - __bfloat162float(h0));
    dl[base + 32 + lane] = __float2bfloat16(y1 - __bfloat162float(h1));
    dl[base + 64 + lane] = __float2bfloat16(y2 - __bfloat162float(h2));
    dl[base + 96 + lane] = __float2bfloat16(y3 - __bfloat162float(h3));
}

// =====================================================================
// Flash attention on mma.sync bf16 (split hi/lo, 3 chains both GEMMs).
// Output written directly as bf16 hi/lo for the WO GEMM.
// =====================================================================
#define FL_STR  136
#define FL_ROWB (FL_STR*2)
#define FL_TILE (64*FL_ROWB)
#define FL_STG  (4*FL_TILE)
#define FL_QLO  (128*FL_ROWB)
#define FL_SMEM (3*FL_STG)

__global__ __launch_bounds__(256, 1) void flash_mma_kernel(
    const __nv_bfloat16* __restrict__ Qh, const __nv_bfloat16* __restrict__ Ql,
    const __nv_bfloat16* __restrict__ Kh, const __nv_bfloat16* __restrict__ Kl,
    const __nv_bfloat16* __restrict__ Vh, const __nv_bfloat16* __restrict__ Vl,
    __nv_bfloat16* __restrict__ Yh, __nv_bfloat16* __restrict__ Yl)
{
    extern __shared__ char smc[];
    const uint32_t sb = smem_to_u32(smc);
    const int t = threadIdx.x;
    const int lane = t & 31;
    const int w = t >> 5;
    const int qi = gridDim.x - 1 - blockIdx.x;
    const int h = blockIdx.y, b = blockIdx.z;
    const int qs = qi * 128;
    const size_t hb = ((size_t)b * SEQ) * EMB + (size_t)h * HDIM;

#pragma unroll
    for (int i = 0; i < 8; i++) {
        const int idx = t + i * 256;
        const int r = idx >> 4, c = idx & 15;
        const size_t g = hb + (size_t)(qs + r) * EMB + c * 8;
        CP_ASYNC16(sb + r * FL_ROWB + c * 16, Qh + g);
        CP_ASYNC16(sb + FL_QLO + r * FL_ROWB + c * 16, Ql + g);
    }
    CP_COMMIT();

    auto load_kv = [&](int s, int ks) {
        const uint32_t base = sb + FL_STG * (1 + s);
        const __nv_bfloat16* srcs[4] = {Kh, Kl, Vh, Vl};
#pragma unroll
        for (int tile = 0; tile < 4; tile++) {
#pragma unroll
            for (int i = 0; i < 4; i++) {
                const int idx = t + i * 256;
                const int r = idx >> 4, c = idx & 15;
                CP_ASYNC16(base + tile * FL_TILE + r * FL_ROWB + c * 16,
                           srcs[tile] + hb + (size_t)(ks + r) * EMB + c * 8);
            }
        }
    };

    load_kv(0, 0);
    CP_COMMIT();

    float m0 = -INFINITY, m1 = -INFINITY, l0 = 0.f, l1 = 0.f;
    float o[16][4];
#pragma unroll
    for (int i = 0; i < 16; i++)
#pragma unroll
        for (int j = 0; j < 4; j++) o[i][j] = 0.f;

    const uint32_t q_addr = sb + (w * 16 + (lane & 15)) * FL_ROWB + (lane >> 4) * 16;
    const int krow = (lane & 7) + ((lane >> 4) << 3);
    const uint32_t kcolb = ((lane >> 3) & 1) * 16;
    const int vrow = (lane & 7) + (((lane >> 3) & 1) << 3);
    const uint32_t vcolb = (lane >> 4) * 16;

    const int r0g = qs + w * 16 + (lane >> 2);
    const int r1g = r0g + 8;
    const int nkt = (qs + 128) / 64;

    for (int jt = 0; jt < nkt; jt++) {
        CP_WAIT0();
        __syncthreads();
        if (jt + 1 < nkt) { load_kv((jt + 1) & 1, (jt + 1) * 64); CP_COMMIT(); }

        const int ks = jt * 64;
        if (ks <= qs + w * 16 + 15) {
            const uint32_t kb = sb + FL_STG * (1 + (jt & 1));

            float s[8][4];
#pragma unroll
            for (int i = 0; i < 8; i++)
#pragma unroll
                for (int j = 0; j < 4; j++) s[i][j] = 0.f;

#pragma unroll
            for (int kf = 0; kf < 8; kf++) {
                uint32_t qa[4], qla[4];
                ldsm4(qa, q_addr + kf * 32);
                ldsm4(qla, q_addr + FL_QLO + kf * 32);
#pragma unroll
                for (int nfp = 0; nfp < 4; nfp++) {
                    uint32_t kh4[4], kl4[4];
                    const uint32_t ka = kb + (nfp * 16 + krow) * FL_ROWB + kcolb + kf * 32;
                    ldsm4(kh4, ka);
                    ldsm4(kl4, ka + FL_TILE);
                    mma_bf16(s[2 * nfp], qa, kh4);
                    mma_bf16(s[2 * nfp], qa, kl4);
                    mma_bf16(s[2 * nfp], qla, kh4);
                    mma_bf16(s[2 * nfp + 1], qa, kh4 + 2);
                    mma_bf16(s[2 * nfp + 1], qa, kl4 + 2);
                    mma_bf16(s[2 * nfp + 1], qla, kh4 + 2);
                }
            }

            if (ks + 63 > r0g) {
#pragma unroll
                for (int nf = 0; nf < 8; nf++) {
                    const int kc = ks + nf * 8 + (lane & 3) * 2;
                    if (kc > r0g)     s[nf][0] = -1e30f;
                    if (kc + 1 > r0g) s[nf][1] = -1e30f;
                    if (kc > r1g)     s[nf][2] = -1e30f;
                    if (kc + 1 > r1g) s[nf][3] = -1e30f;
                }
            }

            float m0l = -INFINITY, m1l = -INFINITY;
#pragma unroll
            for (int nf = 0; nf < 8; nf++) {
                m0l = fmaxf(m0l, fmaxf(s[nf][0], s[nf][1]));
                m1l = fmaxf(m1l, fmaxf(s[nf][2], s[nf][3]));
            }
            m0l = fmaxf(m0l, __shfl_xor_sync(0xffffffffu, m0l, 1));
            m0l = fmaxf(m0l, __shfl_xor_sync(0xffffffffu, m0l, 2));
            m1l = fmaxf(m1l, __shfl_xor_sync(0xffffffffu, m1l, 1));
            m1l = fmaxf(m1l, __shfl_xor_sync(0xffffffffu, m1l, 2));
            const float m0n = fmaxf(m0, m0l), m1n = fmaxf(m1, m1l);
            const float a0 = ex2((m0 - m0n) * L2E);
            const float a1 = ex2((m1 - m1n) * L2E);
            m0 = m0n; m1 = m1n;

            float sum0 = 0.f, sum1 = 0.f;
#pragma unroll
            for (int nf = 0; nf < 8; nf++) {
                s[nf][0] = ex2((s[nf][0] - m0n) * L2E); sum0 += s[nf][0];
                s[nf][1] = ex2((s[nf][1] - m0n) * L2E); sum0 += s[nf][1];
                s[nf][2] = ex2((s[nf][2] - m1n) * L2E); sum1 += s[nf][2];
                s[nf][3] = ex2((s[nf][3] - m1n) * L2E); sum1 += s[nf][3];
            }
            sum0 += __shfl_xor_sync(0xffffffffu, sum0, 1);
            sum0 += __shfl_xor_sync(0xffffffffu, sum0, 2);
            sum1 += __shfl_xor_sync(0xffffffffu, sum1, 1);
            sum1 += __shfl_xor_sync(0xffffffffu, sum1, 2);
            l0 = l0 * a0 + sum0;
            l1 = l1 * a1 + sum1;

#pragma unroll
            for (int nf = 0; nf < 16; nf++) {
                o[nf][0] *= a0; o[nf][1] *= a0;
                o[nf][2] *= a1; o[nf][3] *= a1;
            }

            const uint32_t vb = kb + 2 * FL_TILE;
#pragma unroll
            for (int kf2 = 0; kf2 < 4; kf2++) {
                uint32_t ah[4], al[4];
#pragma unroll
                for (int q2 = 0; q2 < 2; q2++) {
                    const float* sp = s[2 * kf2 + q2];
#pragma unroll
                    for (int rr = 0; rr < 2; rr++) {
                        const float pe = sp[rr * 2], po = sp[rr * 2 + 1];
                        const uint32_t ph = pack_bf16x2(pe, po);
                        const float rle = pe - __uint_as_float(ph << 16);
                        const float rlo = po - __uint_as_float(ph & 0xffff0000u);
                        ah[q2 * 2 + rr] = ph;
                        al[q2 * 2 + rr] = pack_bf16x2(rle, rlo);
                    }
                }
#pragma unroll
                for (int nfp = 0; nfp < 8; nfp++) {
                    uint32_t vh4[4], vl4[4];
                    const uint32_t va = vb + (kf2 * 16 + vrow) * FL_ROWB + vcolb + nfp * 32;
                    ldsm4t(vh4, va);
                    ldsm4t(vl4, va + FL_TILE);
                    mma_bf16(o[2 * nfp], ah, vh4);
                    mma_bf16(o[2 * nfp], ah, vl4);
                    mma_bf16(o[2 * nfp], al, vh4);
                    mma_bf16(o[2 * nfp + 1], ah, vh4 + 2);
                    mma_bf16(o[2 * nfp + 1], ah, vl4 + 2);
                    mma_bf16(o[2 * nfp + 1], al, vh4 + 2);
                }
            }
        }
    }

    const float il0 = 1.f / l0, il1 = 1.f / l1;
    const size_t yb = hb + (size_t)r0g * EMB + (lane & 3) * 2;
#pragma unroll
    for (int nf = 0; nf < 16; nf++) {
        const float a0v = o[nf][0] * il0, a1v = o[nf][1] * il0;
        const float b0v = o[nf][2] * il1, b1v = o[nf][3] * il1;
        const uint32_t h0 = pack_bf16x2(a0v, a1v);
        const uint32_t h1 = pack_bf16x2(b0v, b1v);
        const uint32_t q0 = pack_bf16x2(a0v - __uint_as_float(h0 << 16),
                                        a1v - __uint_as_float(h0 & 0xffff0000u));
        const uint32_t q1 = pack_bf16x2(b0v - __uint_as_float(h1 << 16),
                                        b1v - __uint_as_float(h1 & 0xffff0000u));
        *(uint32_t*)(Yh + yb + nf * 8) = h0;
        *(uint32_t*)(Yl + yb + nf * 8) = q0;
        *(uint32_t*)(Yh + yb + (size_t)8 * EMB + nf * 8) = h1;
        *(uint32_t*)(Yl + yb + (size_t)8 * EMB + nf * 8) = q1;
    }
}

// =====================================================================
// launch
// =====================================================================
extern "C" void kernel_launch(void* const* d_in, const int* in_sizes, int n_in,
                              void* d_out, int out_size)
{
    const float* x  = (const float*)d_in[0];
    const float* wq = (const float*)d_in[1];
    const float* wk = (const float*)d_in[2];
    const float* wv = (const float*)d_in[3];
    const float* wo = (const float*)d_in[4];
    float* out = (float*)d_out;

    float *gq, *gk, *ct, *st;
    __nv_bfloat16 *ahi, *alo, *wthi, *wtlo, *qh, *ql, *kh, *kl, *vh, *vl;
    cudaGetSymbolAddress((void**)&gq, g_q);
    cudaGetSymbolAddress((void**)&gk, g_k);
    cudaGetSymbolAddress((void**)&ct, g_cos);
    cudaGetSymbolAddress((void**)&st, g_sin);
    cudaGetSymbolAddress((void**)&ahi, g_ahi);
    cudaGetSymbolAddress((void**)&alo, g_alo);
    cudaGetSymbolAddress((void**)&wthi, g_wthi);
    cudaGetSymbolAddress((void**)&wtlo, g_wtlo);
    cudaGetSymbolAddress((void**)&qh, g_qh);
    cudaGetSymbolAddress((void**)&ql, g_ql);
    cudaGetSymbolAddress((void**)&kh, g_kh);
    cudaGetSymbolAddress((void**)&kl, g_kl);
    cudaGetSymbolAddress((void**)&vh, g_vh);
    cudaGetSymbolAddress((void**)&vl, g_vl);

    cudaFuncSetAttribute(mma_gemm_kernel,
                         cudaFuncAttributeMaxDynamicSharedMemorySize, GEMM_SMEM);
    cudaFuncSetAttribute(flash_mma_kernel,
                         cudaFuncAttributeMaxDynamicSharedMemorySize, FL_SMEM);

    const int n4 = (int)(ELEMS / 4);
    const dim3 sgrid((n4 + 255) / 256);
    const size_t WSZ = (size_t)EMB * EMB;

    // prep: rope tables, split x, all 4 weights in one launch
    rope_table_kernel<<<(SEQ * 64 + 255) / 256, 256>>>(ct, st);
    split_kernel<<<sgrid, 256>>>(x, ahi, alo, n4);
    dim3 wgrid(EMB / 32, EMB / 32, 4);
    wsplit4_kernel<<<wgrid, 256>>>(wq, wk, wv, wo, wthi, wtlo);

    // fused QKV GEMM: q,k fp32; v directly bf16 hi/lo
    dim3 qkvgrid(3 * EMB / BN, MROWS / BM);   // (24, 64)
    mma_gemm_kernel<<<qkvgrid, 256, GEMM_SMEM>>>(
        ahi, alo, wthi, wtlo, EMB, 1, gq, gk, vh, vl);

    // RoPE + RMSNorm + split, Q and K together (scale folded into Q)
    ropeprep2_kernel<<<2 * BATCH * SEQ * NHEAD / 8, 256>>>(
        gq, gk, ct, st, qh, ql, kh, kl, 0.08838834764831845f);

    // flash attention -> writes ahi/alo (bf16 hi/lo) directly
    dim3 fgrid(SEQ / 128, NHEAD, BATCH);
    flash_mma_kernel<<<fgrid, 256, FL_SMEM>>>(qh, ql, kh, kl, vh, vl, ahi, alo);

    // out = y @ wo
    dim3 ogrid(EMB / BN, MROWS / BM);
    mma_gemm_kernel<<<ogrid, 256, GEMM_SMEM>>>(
        ahi, alo, wthi + 3 * WSZ, wtlo + 3 * WSZ, EMB, 0,
        out, nullptr, nullptr, nullptr);
}

// round 11
// speedup vs baseline: 1.0909x; 1.0285x over previous
#include <cuda_runtime.h>
#include <cuda_bf16.h>
#include <cuda_fp16.h>
#include <math.h>
#include <stdint.h>

// ---------------- constants ----------------
#define BATCH 4
#define SEQ   2048
#define EMB   2048
#define NHEAD 16
#define HDIM  128
#define MROWS (BATCH*SEQ)               // 8192
#define ELEMS ((size_t)BATCH*SEQ*EMB)   // 16777216
#define RMS_EPS 1.1920929e-07f
// softmax: exp(s*scale) = exp2(s * SL2E), SL2E = (1/sqrt(128))*log2(e)
#define SL2E 0.1275290959651556f

// ---------------- scratch (device globals: allocation-free) ----------------
__device__ float g_q[ELEMS];
__device__ float g_k[ELEMS];
__device__ __nv_bfloat16 g_ahi[ELEMS];
__device__ __nv_bfloat16 g_alo[ELEMS];
__device__ __nv_bfloat16 g_wthi[(size_t)4*EMB*EMB];
__device__ __nv_bfloat16 g_wtlo[(size_t)4*EMB*EMB];
__device__ __half g_qh[ELEMS];
__device__ __half g_ql[ELEMS];
__device__ __half g_kh[ELEMS];
__device__ __half g_kl[ELEMS];
__device__ __half g_vh[ELEMS];
__device__ __half g_vl[ELEMS];
__device__ float g_cos[SEQ*64];
__device__ float g_sin[SEQ*64];

// =====================================================================
// PTX helpers (standard sm_80+ instructions; valid on plain sm_103)
// =====================================================================
__device__ __forceinline__ uint32_t smem_to_u32(const void* p) {
    uint32_t a;
    asm("{ .reg .u64 t; cvta.to.shared.u64 t, %1; cvt.u32.u64 %0, t; }"
        : "=r"(a) : "l"(p));
    return a;
}

__device__ __forceinline__ void ldsm4(uint32_t* r, uint32_t addr) {
    asm volatile("ldmatrix.sync.aligned.m8n8.x4.shared.b16 {%0,%1,%2,%3}, [%4];"
        : "=r"(r[0]), "=r"(r[1]), "=r"(r[2]), "=r"(r[3]) : "r"(addr));
}
__device__ __forceinline__ void ldsm4t(uint32_t* r, uint32_t addr) {
    asm volatile("ldmatrix.sync.aligned.m8n8.x4.trans.shared.b16 {%0,%1,%2,%3}, [%4];"
        : "=r"(r[0]), "=r"(r[1]), "=r"(r[2]), "=r"(r[3]) : "r"(addr));
}

__device__ __forceinline__ void mma_bf16(float* c, const uint32_t* a, const uint32_t* b) {
    asm volatile(
        "mma.sync.aligned.m16n8k16.row.col.f32.bf16.bf16.f32 "
        "{%0,%1,%2,%3}, {%4,%5,%6,%7}, {%8,%9}, {%0,%1,%2,%3};"
        : "+f"(c[0]), "+f"(c[1]), "+f"(c[2]), "+f"(c[3])
        : "r"(a[0]), "r"(a[1]), "r"(a[2]), "r"(a[3]), "r"(b[0]), "r"(b[1]));
}

__device__ __forceinline__ void mma_f16(float* c, const uint32_t* a, const uint32_t* b) {
    asm volatile(
        "mma.sync.aligned.m16n8k16.row.col.f32.f16.f16.f32 "
        "{%0,%1,%2,%3}, {%4,%5,%6,%7}, {%8,%9}, {%0,%1,%2,%3};"
        : "+f"(c[0]), "+f"(c[1]), "+f"(c[2]), "+f"(c[3])
        : "r"(a[0]), "r"(a[1]), "r"(a[2]), "r"(a[3]), "r"(b[0]), "r"(b[1]));
}

__device__ __forceinline__ uint32_t pack_bf16x2(float lo, float hi) {
    uint32_t r;
    asm("cvt.rn.bf16x2.f32 %0, %1, %2;" : "=r"(r) : "f"(hi), "f"(lo));
    return r;
}
__device__ __forceinline__ uint32_t pack_f16x2(float lo, float hi) {
    __half2 h = __floats2half2_rn(lo, hi);
    return *(uint32_t*)&h;
}

// fast exp2 (single SASS MUFU.EX2)
__device__ __forceinline__ float ex2(float x) {
    float y;
    asm("ex2.approx.f32 %0, %1;" : "=f"(y) : "f"(x));
    return y;
}

#define CP_ASYNC16(dst, src) \
    asm volatile("cp.async.cg.shared.global [%0], [%1], 16;" :: "r"(dst), "l"(src) : "memory")
#define CP_COMMIT() asm volatile("cp.async.commit_group;" ::: "memory")
#define CP_WAIT0()  asm volatile("cp.async.wait_group 0;" ::: "memory")

// =====================================================================
// split: fp32 -> bf16 hi + bf16 lo (residual)
// =====================================================================
__global__ __launch_bounds__(256) void split_kernel(
    const float* __restrict__ in,
    __nv_bfloat16* __restrict__ hi, __nv_bfloat16* __restrict__ lo, int n4)
{
    int i = blockIdx.x * 256 + threadIdx.x;
    if (i >= n4) return;
    float4 v = ((const float4*)in)[i];
    __nv_bfloat16 h0 = __float2bfloat16(v.x);
    __nv_bfloat16 h1 = __float2bfloat16(v.y);
    __nv_bfloat16 h2 = __float2bfloat16(v.z);
    __nv_bfloat16 h3 = __float2bfloat16(v.w);
    __nv_bfloat16 l0 = __float2bfloat16(v.x - __bfloat162float(h0));
    __nv_bfloat16 l1 = __float2bfloat16(v.y - __bfloat162float(h1));
    __nv_bfloat16 l2 = __float2bfloat16(v.z - __bfloat162float(h2));
    __nv_bfloat16 l3 = __float2bfloat16(v.w - __bfloat162float(h3));
    __nv_bfloat162* hp = (__nv_bfloat162*)(hi + 4 * (size_t)i);
    __nv_bfloat162* lp = (__nv_bfloat162*)(lo + 4 * (size_t)i);
    hp[0] = __nv_bfloat162(h0, h1); hp[1] = __nv_bfloat162(h2, h3);
    lp[0] = __nv_bfloat162(l0, l1); lp[1] = __nv_bfloat162(l2, l3);
}

// =====================================================================
// 4 weights at once: transpose + split, blockIdx.z selects the weight
// =====================================================================
__global__ __launch_bounds__(256) void wsplit4_kernel(
    const float* __restrict__ w0, const float* __restrict__ w1,
    const float* __restrict__ w2, const float* __restrict__ w3,
    __nv_bfloat16* __restrict__ hi_base, __nv_bfloat16* __restrict__ lo_base)
{
    __shared__ float tile[32][33];
    const int z = blockIdx.z;
    const float* w = (z == 0) ? w0 : (z == 1) ? w1 : (z == 2) ? w2 : w3;
    __nv_bfloat16* hi = hi_base + (size_t)z * EMB * EMB;
    __nv_bfloat16* lo = lo_base + (size_t)z * EMB * EMB;

    int n0 = blockIdx.x * 32, k0 = blockIdx.y * 32;
    int tx = threadIdx.x & 31, ty = threadIdx.x >> 5;
#pragma unroll
    for (int i = 0; i < 32; i += 8)
        tile[ty + i][tx] = w[(size_t)(k0 + ty + i) * EMB + n0 + tx];
    __syncthreads();
#pragma unroll
    for (int i = 0; i < 32; i += 8) {
        float v = tile[tx][ty + i];
        __nv_bfloat16 h = __float2bfloat16(v);
        size_t o = (size_t)(n0 + ty + i) * EMB + k0 + tx;
        hi[o] = h;
        lo[o] = __float2bfloat16(v - __bfloat162float(h));
    }
}

// =====================================================================
// RoPE table precompute (double precision, once)
// =====================================================================
__global__ __launch_bounds__(256) void rope_table_kernel(
    float* __restrict__ ct, float* __restrict__ st)
{
    const int idx = blockIdx.x * 256 + threadIdx.x;
    if (idx >= SEQ * 64) return;
    const int tp = idx >> 6, i = idx & 63;
    double inv = exp(-((double)i / 64.0) * log(10000.0));
    double ang = (double)tp * inv;
    double sd, cd;
    sincos(ang, &sd, &cd);
    ct[idx] = (float)cd;
    st[idx] = (float)sd;
}

// =====================================================================
// mma.sync GEMM: C = A * B^T, split bf16 3-chain, 2-stage cp.async,
// ONE __syncthreads per k-iteration.
// Block tile 128x256x64, 8 warps (2 x 4), warp tile 64x64.
// mode 0: write fp32 to c0 (row stride EMB).
// mode 1: QKV fused (N=6144): n<2048 -> c0 fp32, <4096 -> c1 fp32,
//         else V written directly as fp16 hi/lo (c2h/c2l).
// =====================================================================
#define BM 128
#define BN 256
#define BK 64
#define RSTRB 144
#define TA (128 * RSTRB)          // 18432
#define TB (256 * RSTRB)          // 36864
#define STG_B (2*TA + 2*TB)       // 110592
#define GEMM_SMEM (2 * STG_B)     // 221184

__global__ __launch_bounds__(256) void mma_gemm_kernel(
    const __nv_bfloat16* __restrict__ Ahi, const __nv_bfloat16* __restrict__ Alo,
    const __nv_bfloat16* __restrict__ Bhi, const __nv_bfloat16* __restrict__ Blo,
    int K, int mode,
    float* __restrict__ c0, float* __restrict__ c1,
    __half* __restrict__ c2h, __half* __restrict__ c2l)
{
    extern __shared__ char smc[];
    const uint32_t sb = smem_to_u32(smc);
    const int t = threadIdx.x;
    const int lane = t & 31;
    const int wid = t >> 5;
    const int warp_m = wid & 1;
    const int warp_n = wid >> 1;
    const int row0 = blockIdx.y * BM;
    const int col0 = blockIdx.x * BN;

    float acc[4][8][4];
#pragma unroll
    for (int i = 0; i < 4; i++)
#pragma unroll
        for (int j = 0; j < 8; j++)
#pragma unroll
            for (int r = 0; r < 4; r++) acc[i][j][r] = 0.f;

    auto load_stage = [&](int s, int k0) {
        const uint32_t base = sb + s * STG_B;
#pragma unroll
        for (int i = 0; i < 4; i++) {
            const int idx = t + i * 256;
            const int r = idx >> 3, c = idx & 7;
            const size_t g = (size_t)(row0 + r) * K + k0 + c * 8;
            const uint32_t d = base + r * RSTRB + c * 16;
            CP_ASYNC16(d, Ahi + g);
            CP_ASYNC16(d + TA, Alo + g);
        }
#pragma unroll
        for (int i = 0; i < 8; i++) {
            const int idx = t + i * 256;
            const int r = idx >> 3, c = idx & 7;
            const size_t g = (size_t)(col0 + r) * K + k0 + c * 8;
            const uint32_t d = base + 2 * TA + r * RSTRB + c * 16;
            CP_ASYNC16(d, Bhi + g);
            CP_ASYNC16(d + TB, Blo + g);
        }
    };

    const int nIter = K / BK;
    load_stage(0, 0);
    CP_COMMIT();

    for (int it = 0; it < nIter; it++) {
        CP_WAIT0();
        __syncthreads();
        if (it + 1 < nIter) {
            load_stage((it + 1) & 1, (it + 1) * BK);
            CP_COMMIT();
        }

        const uint32_t abase = sb + (it & 1) * STG_B;
        const uint32_t bbase = abase + 2 * TA;
        const int arow = warp_m * 64 + (lane & 15);
        const int brow = warp_n * 64 + ((lane >> 4) << 3) + (lane & 7);

#pragma unroll
        for (int ks = 0; ks < 4; ks++) {
            uint32_t ah[4][4], al[4][4], bh[4][4], bl[4][4];
            const uint32_t acol = ks * 32 + ((lane >> 4) << 4);
            const uint32_t bcol = ks * 32 + (((lane >> 3) & 1) << 4);
#pragma unroll
            for (int mf = 0; mf < 4; mf++) {
                const uint32_t ad = abase + (arow + mf * 16) * RSTRB + acol;
                ldsm4(ah[mf], ad);
                ldsm4(al[mf], ad + TA);
            }
#pragma unroll
            for (int bf = 0; bf < 4; bf++) {
                const uint32_t bd = bbase + (brow + bf * 16) * RSTRB + bcol;
                ldsm4(bh[bf], bd);
                ldsm4(bl[bf], bd + TB);
            }
#pragma unroll
            for (int mf = 0; mf < 4; mf++) {
#pragma unroll
                for (int nf = 0; nf < 8; nf++) {
                    const uint32_t* bhp = &bh[nf >> 1][(nf & 1) * 2];
                    const uint32_t* blp = &bl[nf >> 1][(nf & 1) * 2];
                    mma_bf16(acc[mf][nf], ah[mf], bhp);
                    mma_bf16(acc[mf][nf], ah[mf], blp);
                    mma_bf16(acc[mf][nf], al[mf], bhp);
                }
            }
        }
    }

    // ---- epilogue ----
    const int mbase = row0 + warp_m * 64 + (lane >> 2);
    const int nb = col0 + warp_n * 64 + (lane & 3) * 2;
#pragma unroll
    for (int mf = 0; mf < 4; mf++) {
#pragma unroll
        for (int nf = 0; nf < 8; nf++) {
            const int n = nb + nf * 8;
            const int m0 = mbase + mf * 16;
            const float* a = acc[mf][nf];
            if (mode == 0) {
                const size_t o0 = (size_t)m0 * EMB + n;
                *(float2*)(c0 + o0) = make_float2(a[0], a[1]);
                *(float2*)(c0 + o0 + 8 * EMB) = make_float2(a[2], a[3]);
            } else {
                const int which = n >> 11;
                const int nloc = n & 2047;
                const size_t o0 = (size_t)m0 * EMB + nloc;
                if (which == 0) {
                    *(float2*)(c0 + o0) = make_float2(a[0], a[1]);
                    *(float2*)(c0 + o0 + 8 * EMB) = make_float2(a[2], a[3]);
                } else if (which == 1) {
                    *(float2*)(c1 + o0) = make_float2(a[0], a[1]);
                    *(float2*)(c1 + o0 + 8 * EMB) = make_float2(a[2], a[3]);
                } else {
                    __half e0 = __float2half_rn(a[0]), e1 = __float2half_rn(a[1]);
                    __half e2 = __float2half_rn(a[2]), e3 = __float2half_rn(a[3]);
                    __half2 h0 = __halves2half2(e0, e1);
                    __half2 h1 = __halves2half2(e2, e3);
                    __half2 l0 = __floats2half2_rn(a[0] - __half2float(e0),
                                                   a[1] - __half2float(e1));
                    __half2 l1 = __floats2half2_rn(a[2] - __half2float(e2),
                                                   a[3] - __half2float(e3));
                    *(__half2*)(c2h + o0) = h0;
                    *(__half2*)(c2h + o0 + 8 * EMB) = h1;
                    *(__half2*)(c2l + o0) = l0;
                    *(__half2*)(c2l + o0 + 8 * EMB) = l1;
                }
            }
        }
    }
}

// =====================================================================
// RoPE + RMSNorm + fp16 hi/lo split (NO scale: folded into softmax).
// One WARP per (buffer, b, t, h) head-row; Q and K in one launch.
// =====================================================================
__global__ __launch_bounds__(256) void ropeprep2_kernel(
    const float* __restrict__ q, const float* __restrict__ k,
    const float* __restrict__ ct, const float* __restrict__ st,
    __half* __restrict__ qh, __half* __restrict__ ql,
    __half* __restrict__ kh, __half* __restrict__ kl)
{
    const int w = blockIdx.x * 8 + (threadIdx.x >> 5);
    const int lane = threadIdx.x & 31;
    const int sel = w >> 17;            // 0=Q, 1=K
    const int w2 = w & 131071;
    const int b = w2 >> 15;
    const int r = w2 & 32767;
    const int tp = r >> 4;
    const int h = r & 15;

    const float* buf = sel ? k : q;
    const size_t base = ((size_t)b * SEQ + tp) * EMB + (size_t)h * HDIM;

    const float x1a = buf[base + lane];
    const float x1b = buf[base + 32 + lane];
    const float x2a = buf[base + 64 + lane];
    const float x2b = buf[base + 96 + lane];
    const float ca = ct[tp * 64 + lane],      sa  = st[tp * 64 + lane];
    const float cb = ct[tp * 64 + 32 + lane], sb2 = st[tp * 64 + 32 + lane];

    const float n1a = x1a * ca - x2a * sa;
    const float n2a = x1a * sa + x2a * ca;
    const float n1b = x1b * cb - x2b * sb2;
    const float n2b = x1b * sb2 + x2b * cb;

    float sq = n1a * n1a + n2a * n2a + n1b * n1b + n2b * n2b;
#pragma unroll
    for (int o = 16; o > 0; o >>= 1)
        sq += __shfl_xor_sync(0xffffffffu, sq, o);

    const float rs = rsqrtf(sq * (1.0f / 128.0f) + RMS_EPS);

    __half* dh = sel ? kh : qh;
    __half* dl = sel ? kl : ql;
    const float y0 = n1a * rs, y1 = n1b * rs, y2 = n2a * rs, y3 = n2b * rs;
    __half h0 = __float2half_rn(y0);
    __half h1 = __float2half_rn(y1);
    __half h2 = __float2half_rn(y2);
    __half h3 = __float2half_rn(y3);
    dh[base + lane]      = h0;
    dh[base + 32 + lane] = h1;
    dh[base + 64 + lane] = h2;
    dh[base + 96 + lane] = h3;
    dl[base + lane]      = __float2half_rn(y0 - __half2float(h0));
    dl[base + 32 + lane] = __float2half_rn(y1 - __half2float(h1));
    dl[base + 64 + lane] = __float2half_rn(y2 - __half2float(h2));
    dl[base + 96 + lane] = __float2half_rn(y3 - __half2float(h3));
}

// =====================================================================
// Flash attention, fp16 mma: S = 3 chains (Qh,Ql x Kh,Kl),
// P·V = 2 chains (P fp16 single x Vh,Vl). Q fragments in registers.
// Softmax scale folded into exp2 constant. Output bf16 hi/lo.
// =====================================================================
#define FL_STR  136
#define FL_ROWB (FL_STR*2)
#define FL_TILE (64*FL_ROWB)
#define FL_STG  (4*FL_TILE)
#define FL_QLO  (128*FL_ROWB)
#define FL_SMEM (3*FL_STG)

__global__ __launch_bounds__(256, 1) void flash_mma_kernel(
    const __half* __restrict__ Qh, const __half* __restrict__ Ql,
    const __half* __restrict__ Kh, const __half* __restrict__ Kl,
    const __half* __restrict__ Vh, const __half* __restrict__ Vl,
    __nv_bfloat16* __restrict__ Yh, __nv_bfloat16* __restrict__ Yl)
{
    extern __shared__ char smc[];
    const uint32_t sb = smem_to_u32(smc);
    const int t = threadIdx.x;
    const int lane = t & 31;
    const int w = t >> 5;
    const int qi = gridDim.x - 1 - blockIdx.x;
    const int h = blockIdx.y, b = blockIdx.z;
    const int qs = qi * 128;
    const size_t hb = ((size_t)b * SEQ) * EMB + (size_t)h * HDIM;

#pragma unroll
    for (int i = 0; i < 8; i++) {
        const int idx = t + i * 256;
        const int r = idx >> 4, c = idx & 15;
        const size_t g = hb + (size_t)(qs + r) * EMB + c * 8;
        CP_ASYNC16(sb + r * FL_ROWB + c * 16, Qh + g);
        CP_ASYNC16(sb + FL_QLO + r * FL_ROWB + c * 16, Ql + g);
    }
    CP_COMMIT();

    auto load_kv = [&](int s, int ks) {
        const uint32_t base = sb + FL_STG * (1 + s);
        const __half* srcs[4] = {Kh, Kl, Vh, Vl};
#pragma unroll
        for (int tile = 0; tile < 4; tile++) {
#pragma unroll
            for (int i = 0; i < 4; i++) {
                const int idx = t + i * 256;
                const int r = idx >> 4, c = idx & 15;
                CP_ASYNC16(base + tile * FL_TILE + r * FL_ROWB + c * 16,
                           srcs[tile] + hb + (size_t)(ks + r) * EMB + c * 8);
            }
        }
    };

    load_kv(0, 0);
    CP_COMMIT();

    float m0 = -INFINITY, m1 = -INFINITY, l0 = 0.f, l1 = 0.f;
    float o[16][4];
#pragma unroll
    for (int i = 0; i < 16; i++)
#pragma unroll
        for (int j = 0; j < 4; j++) o[i][j] = 0.f;

    const uint32_t q_addr = sb + (w * 16 + (lane & 15)) * FL_ROWB + (lane >> 4) * 16;
    const int krow = (lane & 7) + ((lane >> 4) << 3);
    const uint32_t kcolb = ((lane >> 3) & 1) * 16;
    const int vrow = (lane & 7) + (((lane >> 3) & 1) << 3);
    const uint32_t vcolb = (lane >> 4) * 16;

    const int r0g = qs + w * 16 + (lane >> 2);
    const int r1g = r0g + 8;
    const int nkt = (qs + 128) / 64;

    // ---- preload Q fragments into registers (Q + KV0 already awaited) ----
    CP_WAIT0();
    __syncthreads();
    uint32_t qa_r[8][4], qla_r[8][4];
#pragma unroll
    for (int kf = 0; kf < 8; kf++) {
        ldsm4(qa_r[kf], q_addr + kf * 32);
        ldsm4(qla_r[kf], q_addr + FL_QLO + kf * 32);
    }

    for (int jt = 0; jt < nkt; jt++) {
        CP_WAIT0();
        __syncthreads();
        if (jt + 1 < nkt) { load_kv((jt + 1) & 1, (jt + 1) * 64); CP_COMMIT(); }

        const int ks = jt * 64;
        if (ks <= qs + w * 16 + 15) {
            const uint32_t kb = sb + FL_STG * (1 + (jt & 1));

            float s[8][4];
#pragma unroll
            for (int i = 0; i < 8; i++)
#pragma unroll
                for (int j = 0; j < 4; j++) s[i][j] = 0.f;

#pragma unroll
            for (int kf = 0; kf < 8; kf++) {
#pragma unroll
                for (int nfp = 0; nfp < 4; nfp++) {
                    uint32_t kh4[4], kl4[4];
                    const uint32_t ka = kb + (nfp * 16 + krow) * FL_ROWB + kcolb + kf * 32;
                    ldsm4(kh4, ka);
                    ldsm4(kl4, ka + FL_TILE);
                    mma_f16(s[2 * nfp], qa_r[kf], kh4);
                    mma_f16(s[2 * nfp], qa_r[kf], kl4);
                    mma_f16(s[2 * nfp], qla_r[kf], kh4);
                    mma_f16(s[2 * nfp + 1], qa_r[kf], kh4 + 2);
                    mma_f16(s[2 * nfp + 1], qa_r[kf], kl4 + 2);
                    mma_f16(s[2 * nfp + 1], qla_r[kf], kh4 + 2);
                }
            }

            if (ks + 63 > r0g) {
#pragma unroll
                for (int nf = 0; nf < 8; nf++) {
                    const int kc = ks + nf * 8 + (lane & 3) * 2;
                    if (kc > r0g)     s[nf][0] = -1e30f;
                    if (kc + 1 > r0g) s[nf][1] = -1e30f;
                    if (kc > r1g)     s[nf][2] = -1e30f;
                    if (kc + 1 > r1g) s[nf][3] = -1e30f;
                }
            }

            float m0l = -INFINITY, m1l = -INFINITY;
#pragma unroll
            for (int nf = 0; nf < 8; nf++) {
                m0l = fmaxf(m0l, fmaxf(s[nf][0], s[nf][1]));
                m1l = fmaxf(m1l, fmaxf(s[nf][2], s[nf][3]));
            }
            m0l = fmaxf(m0l, __shfl_xor_sync(0xffffffffu, m0l, 1));
            m0l = fmaxf(m0l, __shfl_xor_sync(0xffffffffu, m0l, 2));
            m1l = fmaxf(m1l, __shfl_xor_sync(0xffffffffu, m1l, 1));
            m1l = fmaxf(m1l, __shfl_xor_sync(0xffffffffu, m1l, 2));
            const float m0n = fmaxf(m0, m0l), m1n = fmaxf(m1, m1l);
            const float a0 = ex2((m0 - m0n) * SL2E);
            const float a1 = ex2((m1 - m1n) * SL2E);
            m0 = m0n; m1 = m1n;

            float sum0 = 0.f, sum1 = 0.f;
#pragma unroll
            for (int nf = 0; nf < 8; nf++) {
                s[nf][0] = ex2((s[nf][0] - m0n) * SL2E); sum0 += s[nf][0];
                s[nf][1] = ex2((s[nf][1] - m0n) * SL2E); sum0 += s[nf][1];
                s[nf][2] = ex2((s[nf][2] - m1n) * SL2E); sum1 += s[nf][2];
                s[nf][3] = ex2((s[nf][3] - m1n) * SL2E); sum1 += s[nf][3];
            }
            sum0 += __shfl_xor_sync(0xffffffffu, sum0, 1);
            sum0 += __shfl_xor_sync(0xffffffffu, sum0, 2);
            sum1 += __shfl_xor_sync(0xffffffffu, sum1, 1);
            sum1 += __shfl_xor_sync(0xffffffffu, sum1, 2);
            l0 = l0 * a0 + sum0;
            l1 = l1 * a1 + sum1;

#pragma unroll
            for (int nf = 0; nf < 16; nf++) {
                o[nf][0] *= a0; o[nf][1] *= a0;
                o[nf][2] *= a1; o[nf][3] *= a1;
            }

            // ---- O += P V : P single fp16, V hi/lo (2 chains) ----
            const uint32_t vb = kb + 2 * FL_TILE;
#pragma unroll
            for (int kf2 = 0; kf2 < 4; kf2++) {
                uint32_t ah[4];
#pragma unroll
                for (int q2 = 0; q2 < 2; q2++) {
                    const float* sp = s[2 * kf2 + q2];
                    ah[q2 * 2 + 0] = pack_f16x2(sp[0], sp[1]);
                    ah[q2 * 2 + 1] = pack_f16x2(sp[2], sp[3]);
                }
#pragma unroll
                for (int nfp = 0; nfp < 8; nfp++) {
                    uint32_t vh4[4], vl4[4];
                    const uint32_t va = vb + (kf2 * 16 + vrow) * FL_ROWB + vcolb + nfp * 32;
                    ldsm4t(vh4, va);
                    ldsm4t(vl4, va + FL_TILE);
                    mma_f16(o[2 * nfp], ah, vh4);
                    mma_f16(o[2 * nfp], ah, vl4);
                    mma_f16(o[2 * nfp + 1], ah, vh4 + 2);
                    mma_f16(o[2 * nfp + 1], ah, vl4 + 2);
                }
            }
        }
    }

    const float il0 = 1.f / l0, il1 = 1.f / l1;
    const size_t yb = hb + (size_t)r0g * EMB + (lane & 3) * 2;
#pragma unroll
    for (int nf = 0; nf < 16; nf++) {
        const float a0v = o[nf][0] * il0, a1v = o[nf][1] * il0;
        const float b0v = o[nf][2] * il1, b1v = o[nf][3] * il1;
        const uint32_t h0 = pack_bf16x2(a0v, a1v);
        const uint32_t h1 = pack_bf16x2(b0v, b1v);
        const uint32_t q0 = pack_bf16x2(a0v - __uint_as_float(h0 << 16),
                                        a1v - __uint_as_float(h0 & 0xffff0000u));
        const uint32_t q1 = pack_bf16x2(b0v - __uint_as_float(h1 << 16),
                                        b1v - __uint_as_float(h1 & 0xffff0000u));
        *(uint32_t*)(Yh + yb + nf * 8) = h0;
        *(uint32_t*)(Yl + yb + nf * 8) = q0;
        *(uint32_t*)(Yh + yb + (size_t)8 * EMB + nf * 8) = h1;
        *(uint32_t*)(Yl + yb + (size_t)8 * EMB + nf * 8) = q1;
    }
}

// =====================================================================
// launch
// =====================================================================
extern "C" void kernel_launch(void* const* d_in, const int* in_sizes, int n_in,
                              void* d_out, int out_size)
{
    const float* x  = (const float*)d_in[0];
    const float* wq = (const float*)d_in[1];
    const float* wk = (const float*)d_in[2];
    const float* wv = (const float*)d_in[3];
    const float* wo = (const float*)d_in[4];
    float* out = (float*)d_out;

    float *gq, *gk, *ct, *st;
    __nv_bfloat16 *ahi, *alo, *wthi, *wtlo;
    __half *qh, *ql, *kh, *kl, *vh, *vl;
    cudaGetSymbolAddress((void**)&gq, g_q);
    cudaGetSymbolAddress((void**)&gk, g_k);
    cudaGetSymbolAddress((void**)&ct, g_cos);
    cudaGetSymbolAddress((void**)&st, g_sin);
    cudaGetSymbolAddress((void**)&ahi, g_ahi);
    cudaGetSymbolAddress((void**)&alo, g_alo);
    cudaGetSymbolAddress((void**)&wthi, g_wthi);
    cudaGetSymbolAddress((void**)&wtlo, g_wtlo);
    cudaGetSymbolAddress((void**)&qh, g_qh);
    cudaGetSymbolAddress((void**)&ql, g_ql);
    cudaGetSymbolAddress((void**)&kh, g_kh);
    cudaGetSymbolAddress((void**)&kl, g_kl);
    cudaGetSymbolAddress((void**)&vh, g_vh);
    cudaGetSymbolAddress((void**)&vl, g_vl);

    cudaFuncSetAttribute(mma_gemm_kernel,
                         cudaFuncAttributeMaxDynamicSharedMemorySize, GEMM_SMEM);
    cudaFuncSetAttribute(flash_mma_kernel,
                         cudaFuncAttributeMaxDynamicSharedMemorySize, FL_SMEM);

    const int n4 = (int)(ELEMS / 4);
    const dim3 sgrid((n4 + 255) / 256);
    const size_t WSZ = (size_t)EMB * EMB;

    // prep: rope tables, split x, all 4 weights in one launch
    rope_table_kernel<<<(SEQ * 64 + 255) / 256, 256>>>(ct, st);
    split_kernel<<<sgrid, 256>>>(x, ahi, alo, n4);
    dim3 wgrid(EMB / 32, EMB / 32, 4);
    wsplit4_kernel<<<wgrid, 256>>>(wq, wk, wv, wo, wthi, wtlo);

    // fused QKV GEMM: q,k fp32; v directly fp16 hi/lo
    dim3 qkvgrid(3 * EMB / BN, MROWS / BM);   // (24, 64)
    mma_gemm_kernel<<<qkvgrid, 256, GEMM_SMEM>>>(
        ahi, alo, wthi, wtlo, EMB, 1, gq, gk, vh, vl);

    // RoPE + RMSNorm + fp16 split, Q and K together (no scale)
    ropeprep2_kernel<<<2 * BATCH * SEQ * NHEAD / 8, 256>>>(
        gq, gk, ct, st, qh, ql, kh, kl);

    // flash attention -> writes ahi/alo (bf16 hi/lo) directly
    dim3 fgrid(SEQ / 128, NHEAD, BATCH);
    flash_mma_kernel<<<fgrid, 256, FL_SMEM>>>(qh, ql, kh, kl, vh, vl, ahi, alo);

    // out = y @ wo
    dim3 ogrid(EMB / BN, MROWS / BM);
    mma_gemm_kernel<<<ogrid, 256, GEMM_SMEM>>>(
        ahi, alo, wthi + 3 * WSZ, wtlo + 3 * WSZ, EMB, 0,
        out, nullptr, nullptr, nullptr);
}

// round 12
// speedup vs baseline: 1.3788x; 1.2639x over previous
#include <cuda_runtime.h>
#include <cuda_bf16.h>
#include <cuda_fp16.h>
#include <math.h>
#include <stdint.h>

// ---------------- constants ----------------
#define BATCH 4
#define SEQ   2048
#define EMB   2048
#define NHEAD 16
#define HDIM  128
#define MROWS (BATCH*SEQ)               // 8192
#define ELEMS ((size_t)BATCH*SEQ*EMB)   // 16777216
#define RMS_EPS 1.1920929e-07f
// softmax: exp(s*scale) = exp2(s * SL2E), SL2E = (1/sqrt(128))*log2(e)
#define SL2E 0.1275290959651556f
#define WSCALE 64.0f
#define WINV   0.015625f

// ---------------- scratch (device globals: allocation-free) ----------------
__device__ float g_q[ELEMS];
__device__ float g_k[ELEMS];
__device__ __half g_a[ELEMS];                      // fp16 A operand (x, then Y)
__device__ __half g_wthi[(size_t)4*EMB*EMB];       // transposed weights (x64) hi
__device__ __half g_wtlo[(size_t)4*EMB*EMB];       // lo
__device__ __half g_qh[ELEMS];
__device__ __half g_ql[ELEMS];
__device__ __half g_kh[ELEMS];
__device__ __half g_kl[ELEMS];
__device__ __half g_vh[ELEMS];
__device__ __half g_vl[ELEMS];
__device__ float g_cos[SEQ*64];
__device__ float g_sin[SEQ*64];

// =====================================================================
// PTX helpers (standard sm_80+ instructions; valid on plain sm_103)
// =====================================================================
__device__ __forceinline__ uint32_t smem_to_u32(const void* p) {
    uint32_t a;
    asm("{ .reg .u64 t; cvta.to.shared.u64 t, %1; cvt.u32.u64 %0, t; }"
        : "=r"(a) : "l"(p));
    return a;
}

__device__ __forceinline__ void ldsm4(uint32_t* r, uint32_t addr) {
    asm volatile("ldmatrix.sync.aligned.m8n8.x4.shared.b16 {%0,%1,%2,%3}, [%4];"
        : "=r"(r[0]), "=r"(r[1]), "=r"(r[2]), "=r"(r[3]) : "r"(addr));
}
__device__ __forceinline__ void ldsm4t(uint32_t* r, uint32_t addr) {
    asm volatile("ldmatrix.sync.aligned.m8n8.x4.trans.shared.b16 {%0,%1,%2,%3}, [%4];"
        : "=r"(r[0]), "=r"(r[1]), "=r"(r[2]), "=r"(r[3]) : "r"(addr));
}

__device__ __forceinline__ void mma_f16(float* c, const uint32_t* a, const uint32_t* b) {
    asm volatile(
        "mma.sync.aligned.m16n8k16.row.col.f32.f16.f16.f32 "
        "{%0,%1,%2,%3}, {%4,%5,%6,%7}, {%8,%9}, {%0,%1,%2,%3};"
        : "+f"(c[0]), "+f"(c[1]), "+f"(c[2]), "+f"(c[3])
        : "r"(a[0]), "r"(a[1]), "r"(a[2]), "r"(a[3]), "r"(b[0]), "r"(b[1]));
}

__device__ __forceinline__ uint32_t pack_f16x2(float lo, float hi) {
    __half2 h = __floats2half2_rn(lo, hi);
    return *(uint32_t*)&h;
}

// fast exp2 (single SASS MUFU.EX2)
__device__ __forceinline__ float ex2(float x) {
    float y;
    asm("ex2.approx.f32 %0, %1;" : "=f"(y) : "f"(x));
    return y;
}

#define CP_ASYNC16(dst, src) \
    asm volatile("cp.async.cg.shared.global [%0], [%1], 16;" :: "r"(dst), "l"(src) : "memory")
#define CP_COMMIT() asm volatile("cp.async.commit_group;" ::: "memory")
#define CP_WAIT0()  asm volatile("cp.async.wait_group 0;" ::: "memory")

// =====================================================================
// conv16: fp32 -> fp16 (single)
// =====================================================================
__global__ __launch_bounds__(256) void conv16_kernel(
    const float* __restrict__ in, __half* __restrict__ out, int n4)
{
    int i = blockIdx.x * 256 + threadIdx.x;
    if (i >= n4) return;
    float4 v = ((const float4*)in)[i];
    uint2 o;
    o.x = pack_f16x2(v.x, v.y);
    o.y = pack_f16x2(v.z, v.w);
    ((uint2*)out)[i] = o;
}

// =====================================================================
// 4 weights: transpose + x64 scale + fp16 hi/lo split
// =====================================================================
__global__ __launch_bounds__(256) void wsplit4_kernel(
    const float* __restrict__ w0, const float* __restrict__ w1,
    const float* __restrict__ w2, const float* __restrict__ w3,
    __half* __restrict__ hi_base, __half* __restrict__ lo_base)
{
    __shared__ float tile[32][33];
    const int z = blockIdx.z;
    const float* w = (z == 0) ? w0 : (z == 1) ? w1 : (z == 2) ? w2 : w3;
    __half* hi = hi_base + (size_t)z * EMB * EMB;
    __half* lo = lo_base + (size_t)z * EMB * EMB;

    int n0 = blockIdx.x * 32, k0 = blockIdx.y * 32;
    int tx = threadIdx.x & 31, ty = threadIdx.x >> 5;
#pragma unroll
    for (int i = 0; i < 32; i += 8)
        tile[ty + i][tx] = w[(size_t)(k0 + ty + i) * EMB + n0 + tx];
    __syncthreads();
#pragma unroll
    for (int i = 0; i < 32; i += 8) {
        float v = tile[tx][ty + i] * WSCALE;
        __half h = __float2half_rn(v);
        size_t o = (size_t)(n0 + ty + i) * EMB + k0 + tx;
        hi[o] = h;
        lo[o] = __float2half_rn(v - __half2float(h));
    }
}

// =====================================================================
// RoPE table precompute (double precision, once)
// =====================================================================
__global__ __launch_bounds__(256) void rope_table_kernel(
    float* __restrict__ ct, float* __restrict__ st)
{
    const int idx = blockIdx.x * 256 + threadIdx.x;
    if (idx >= SEQ * 64) return;
    const int tp = idx >> 6, i = idx & 63;
    double inv = exp(-((double)i / 64.0) * log(10000.0));
    double ang = (double)tp * inv;
    double sd, cd;
    sincos(ang, &sd, &cd);
    ct[idx] = (float)cd;
    st[idx] = (float)sd;
}

// =====================================================================
// mma.sync GEMM: C = (A * B^T)/64.  A single fp16; B fp16 hi/lo (x64).
// 2 chains: A*Bhi + A*Blo.  2-stage cp.async, ONE sync per k-iter.
// Block tile 128x256x64, 8 warps (2 x 4), warp tile 64x64.
// mode 0: fp32 -> c0.  mode 1 (QKV fused, N=6144): q,k fp32; V fp16 hi/lo.
// =====================================================================
#define BM 128
#define BN 256
#define BK 64
#define RSTRB 144
#define TA (128 * RSTRB)          // 18432 (A: one tile)
#define TB (256 * RSTRB)          // 36864
#define STG_B (TA + 2*TB)         // 92160
#define GEMM_SMEM (2 * STG_B)     // 184320

__global__ __launch_bounds__(256) void mma_gemm_kernel(
    const __half* __restrict__ A,
    const __half* __restrict__ Bhi, const __half* __restrict__ Blo,
    int K, int mode,
    float* __restrict__ c0, float* __restrict__ c1,
    __half* __restrict__ c2h, __half* __restrict__ c2l)
{
    extern __shared__ char smc[];
    const uint32_t sb = smem_to_u32(smc);
    const int t = threadIdx.x;
    const int lane = t & 31;
    const int wid = t >> 5;
    const int warp_m = wid & 1;
    const int warp_n = wid >> 1;
    const int row0 = blockIdx.y * BM;
    const int col0 = blockIdx.x * BN;

    float acc[4][8][4];
#pragma unroll
    for (int i = 0; i < 4; i++)
#pragma unroll
        for (int j = 0; j < 8; j++)
#pragma unroll
            for (int r = 0; r < 4; r++) acc[i][j][r] = 0.f;

    auto load_stage = [&](int s, int k0) {
        const uint32_t base = sb + s * STG_B;
#pragma unroll
        for (int i = 0; i < 4; i++) {
            const int idx = t + i * 256;
            const int r = idx >> 3, c = idx & 7;
            CP_ASYNC16(base + r * RSTRB + c * 16,
                       A + (size_t)(row0 + r) * K + k0 + c * 8);
        }
#pragma unroll
        for (int i = 0; i < 8; i++) {
            const int idx = t + i * 256;
            const int r = idx >> 3, c = idx & 7;
            const size_t g = (size_t)(col0 + r) * K + k0 + c * 8;
            const uint32_t d = base + TA + r * RSTRB + c * 16;
            CP_ASYNC16(d, Bhi + g);
            CP_ASYNC16(d + TB, Blo + g);
        }
    };

    const int nIter = K / BK;
    load_stage(0, 0);
    CP_COMMIT();

    for (int it = 0; it < nIter; it++) {
        CP_WAIT0();
        __syncthreads();
        if (it + 1 < nIter) {
            load_stage((it + 1) & 1, (it + 1) * BK);
            CP_COMMIT();
        }

        const uint32_t abase = sb + (it & 1) * STG_B;
        const uint32_t bbase = abase + TA;
        const int arow = warp_m * 64 + (lane & 15);
        const int brow = warp_n * 64 + ((lane >> 4) << 3) + (lane & 7);

#pragma unroll
        for (int ks = 0; ks < 4; ks++) {
            uint32_t ah[4][4], bh[4][4], bl[4][4];
            const uint32_t acol = ks * 32 + ((lane >> 4) << 4);
            const uint32_t bcol = ks * 32 + (((lane >> 3) & 1) << 4);
#pragma unroll
            for (int mf = 0; mf < 4; mf++)
                ldsm4(ah[mf], abase + (arow + mf * 16) * RSTRB + acol);
#pragma unroll
            for (int bf = 0; bf < 4; bf++) {
                const uint32_t bd = bbase + (brow + bf * 16) * RSTRB + bcol;
                ldsm4(bh[bf], bd);
                ldsm4(bl[bf], bd + TB);
            }
#pragma unroll
            for (int mf = 0; mf < 4; mf++) {
#pragma unroll
                for (int nf = 0; nf < 8; nf++) {
                    const uint32_t* bhp = &bh[nf >> 1][(nf & 1) * 2];
                    const uint32_t* blp = &bl[nf >> 1][(nf & 1) * 2];
                    mma_f16(acc[mf][nf], ah[mf], bhp);
                    mma_f16(acc[mf][nf], ah[mf], blp);
                }
            }
        }
    }

    // ---- epilogue (unscale by 1/64) ----
    const int mbase = row0 + warp_m * 64 + (lane >> 2);
    const int nb = col0 + warp_n * 64 + (lane & 3) * 2;
#pragma unroll
    for (int mf = 0; mf < 4; mf++) {
#pragma unroll
        for (int nf = 0; nf < 8; nf++) {
            const int n = nb + nf * 8;
            const int m0 = mbase + mf * 16;
            float a0 = acc[mf][nf][0] * WINV, a1 = acc[mf][nf][1] * WINV;
            float a2 = acc[mf][nf][2] * WINV, a3 = acc[mf][nf][3] * WINV;
            if (mode == 0) {
                const size_t o0 = (size_t)m0 * EMB + n;
                *(float2*)(c0 + o0) = make_float2(a0, a1);
                *(float2*)(c0 + o0 + 8 * EMB) = make_float2(a2, a3);
            } else {
                const int which = n >> 11;
                const int nloc = n & 2047;
                const size_t o0 = (size_t)m0 * EMB + nloc;
                if (which == 0) {
                    *(float2*)(c0 + o0) = make_float2(a0, a1);
                    *(float2*)(c0 + o0 + 8 * EMB) = make_float2(a2, a3);
                } else if (which == 1) {
                    *(float2*)(c1 + o0) = make_float2(a0, a1);
                    *(float2*)(c1 + o0 + 8 * EMB) = make_float2(a2, a3);
                } else {
                    __half e0 = __float2half_rn(a0), e1 = __float2half_rn(a1);
                    __half e2 = __float2half_rn(a2), e3 = __float2half_rn(a3);
                    *(__half2*)(c2h + o0) = __halves2half2(e0, e1);
                    *(__half2*)(c2h + o0 + 8 * EMB) = __halves2half2(e2, e3);
                    *(__half2*)(c2l + o0) = __floats2half2_rn(a0 - __half2float(e0),
                                                              a1 - __half2float(e1));
                    *(__half2*)(c2l + o0 + 8 * EMB) = __floats2half2_rn(a2 - __half2float(e2),
                                                                        a3 - __half2float(e3));
                }
            }
        }
    }
}

// =====================================================================
// RoPE + RMSNorm + fp16 hi/lo split (NO scale: folded into softmax).
// One WARP per (buffer, b, t, h) head-row; Q and K in one launch.
// =====================================================================
__global__ __launch_bounds__(256) void ropeprep2_kernel(
    const float* __restrict__ q, const float* __restrict__ k,
    const float* __restrict__ ct, const float* __restrict__ st,
    __half* __restrict__ qh, __half* __restrict__ ql,
    __half* __restrict__ kh, __half* __restrict__ kl)
{
    const int w = blockIdx.x * 8 + (threadIdx.x >> 5);
    const int lane = threadIdx.x & 31;
    const int sel = w >> 17;            // 0=Q, 1=K
    const int w2 = w & 131071;
    const int b = w2 >> 15;
    const int r = w2 & 32767;
    const int tp = r >> 4;
    const int h = r & 15;

    const float* buf = sel ? k : q;
    const size_t base = ((size_t)b * SEQ + tp) * EMB + (size_t)h * HDIM;

    const float x1a = buf[base + lane];
    const float x1b = buf[base + 32 + lane];
    const float x2a = buf[base + 64 + lane];
    const float x2b = buf[base + 96 + lane];
    const float ca = ct[tp * 64 + lane],      sa  = st[tp * 64 + lane];
    const float cb = ct[tp * 64 + 32 + lane], sb2 = st[tp * 64 + 32 + lane];

    const float n1a = x1a * ca - x2a * sa;
    const float n2a = x1a * sa + x2a * ca;
    const float n1b = x1b * cb - x2b * sb2;
    const float n2b = x1b * sb2 + x2b * cb;

    float sq = n1a * n1a + n2a * n2a + n1b * n1b + n2b * n2b;
#pragma unroll
    for (int o = 16; o > 0; o >>= 1)
        sq += __shfl_xor_sync(0xffffffffu, sq, o);

    const float rs = rsqrtf(sq * (1.0f / 128.0f) + RMS_EPS);

    __half* dh = sel ? kh : qh;
    __half* dl = sel ? kl : ql;
    const float y0 = n1a * rs, y1 = n1b * rs, y2 = n2a * rs, y3 = n2b * rs;
    __half h0 = __float2half_rn(y0);
    __half h1 = __float2half_rn(y1);
    __half h2 = __float2half_rn(y2);
    __half h3 = __float2half_rn(y3);
    dh[base + lane]      = h0;
    dh[base + 32 + lane] = h1;
    dh[base + 64 + lane] = h2;
    dh[base + 96 + lane] = h3;
    dl[base + lane]      = __float2half_rn(y0 - __half2float(h0));
    dl[base + 32 + lane] = __float2half_rn(y1 - __half2float(h1));
    dl[base + 64 + lane] = __float2half_rn(y2 - __half2float(h2));
    dl[base + 96 + lane] = __float2half_rn(y3 - __half2float(h3));
}

// =====================================================================
// Flash attention, fp16 mma: S = 3 chains (Qh,Ql x Kh,Kl),
// P·V = 2 chains (P fp16 single x Vh,Vl). Q fragments in registers.
// Softmax scale folded into exp2 constant. Output fp16 single (for WO).
// =====================================================================
#define FL_STR  136
#define FL_ROWB (FL_STR*2)
#define FL_TILE (64*FL_ROWB)
#define FL_STG  (4*FL_TILE)
#define FL_QLO  (128*FL_ROWB)
#define FL_SMEM (3*FL_STG)

__global__ __launch_bounds__(256, 1) void flash_mma_kernel(
    const __half* __restrict__ Qh, const __half* __restrict__ Ql,
    const __half* __restrict__ Kh, const __half* __restrict__ Kl,
    const __half* __restrict__ Vh, const __half* __restrict__ Vl,
    __half* __restrict__ Y)
{
    extern __shared__ char smc[];
    const uint32_t sb = smem_to_u32(smc);
    const int t = threadIdx.x;
    const int lane = t & 31;
    const int w = t >> 5;
    const int qi = gridDim.x - 1 - blockIdx.x;
    const int h = blockIdx.y, b = blockIdx.z;
    const int qs = qi * 128;
    const size_t hb = ((size_t)b * SEQ) * EMB + (size_t)h * HDIM;

#pragma unroll
    for (int i = 0; i < 8; i++) {
        const int idx = t + i * 256;
        const int r = idx >> 4, c = idx & 15;
        const size_t g = hb + (size_t)(qs + r) * EMB + c * 8;
        CP_ASYNC16(sb + r * FL_ROWB + c * 16, Qh + g);
        CP_ASYNC16(sb + FL_QLO + r * FL_ROWB + c * 16, Ql + g);
    }
    CP_COMMIT();

    auto load_kv = [&](int s, int ks) {
        const uint32_t base = sb + FL_STG * (1 + s);
        const __half* srcs[4] = {Kh, Kl, Vh, Vl};
#pragma unroll
        for (int tile = 0; tile < 4; tile++) {
#pragma unroll
            for (int i = 0; i < 4; i++) {
                const int idx = t + i * 256;
                const int r = idx >> 4, c = idx & 15;
                CP_ASYNC16(base + tile * FL_TILE + r * FL_ROWB + c * 16,
                           srcs[tile] + hb + (size_t)(ks + r) * EMB + c * 8);
            }
        }
    };

    load_kv(0, 0);
    CP_COMMIT();

    float m0 = -INFINITY, m1 = -INFINITY, l0 = 0.f, l1 = 0.f;
    float o[16][4];
#pragma unroll
    for (int i = 0; i < 16; i++)
#pragma unroll
        for (int j = 0; j < 4; j++) o[i][j] = 0.f;

    const uint32_t q_addr = sb + (w * 16 + (lane & 15)) * FL_ROWB + (lane >> 4) * 16;
    const int krow = (lane & 7) + ((lane >> 4) << 3);
    const uint32_t kcolb = ((lane >> 3) & 1) * 16;
    const int vrow = (lane & 7) + (((lane >> 3) & 1) << 3);
    const uint32_t vcolb = (lane >> 4) * 16;

    const int r0g = qs + w * 16 + (lane >> 2);
    const int r1g = r0g + 8;
    const int nkt = (qs + 128) / 64;

    // ---- preload Q fragments into registers ----
    CP_WAIT0();
    __syncthreads();
    uint32_t qa_r[8][4], qla_r[8][4];
#pragma unroll
    for (int kf = 0; kf < 8; kf++) {
        ldsm4(qa_r[kf], q_addr + kf * 32);
        ldsm4(qla_r[kf], q_addr + FL_QLO + kf * 32);
    }

    for (int jt = 0; jt < nkt; jt++) {
        CP_WAIT0();
        __syncthreads();
        if (jt + 1 < nkt) { load_kv((jt + 1) & 1, (jt + 1) * 64); CP_COMMIT(); }

        const int ks = jt * 64;
        if (ks <= qs + w * 16 + 15) {
            const uint32_t kb = sb + FL_STG * (1 + (jt & 1));

            float s[8][4];
#pragma unroll
            for (int i = 0; i < 8; i++)
#pragma unroll
                for (int j = 0; j < 4; j++) s[i][j] = 0.f;

#pragma unroll
            for (int kf = 0; kf < 8; kf++) {
#pragma unroll
                for (int nfp = 0; nfp < 4; nfp++) {
                    uint32_t kh4[4], kl4[4];
                    const uint32_t ka = kb + (nfp * 16 + krow) * FL_ROWB + kcolb + kf * 32;
                    ldsm4(kh4, ka);
                    ldsm4(kl4, ka + FL_TILE);
                    mma_f16(s[2 * nfp], qa_r[kf], kh4);
                    mma_f16(s[2 * nfp], qa_r[kf], kl4);
                    mma_f16(s[2 * nfp], qla_r[kf], kh4);
                    mma_f16(s[2 * nfp + 1], qa_r[kf], kh4 + 2);
                    mma_f16(s[2 * nfp + 1], qa_r[kf], kl4 + 2);
                    mma_f16(s[2 * nfp + 1], qla_r[kf], kh4 + 2);
                }
            }

            if (ks + 63 > r0g) {
#pragma unroll
                for (int nf = 0; nf < 8; nf++) {
                    const int kc = ks + nf * 8 + (lane & 3) * 2;
                    if (kc > r0g)     s[nf][0] = -1e30f;
                    if (kc + 1 > r0g) s[nf][1] = -1e30f;
                    if (kc > r1g)     s[nf][2] = -1e30f;
                    if (kc + 1 > r1g) s[nf][3] = -1e30f;
                }
            }

            float m0l = -INFINITY, m1l = -INFINITY;
#pragma unroll
            for (int nf = 0; nf < 8; nf++) {
                m0l = fmaxf(m0l, fmaxf(s[nf][0], s[nf][1]));
                m1l = fmaxf(m1l, fmaxf(s[nf][2], s[nf][3]));
            }
            m0l = fmaxf(m0l, __shfl_xor_sync(0xffffffffu, m0l, 1));
            m0l = fmaxf(m0l, __shfl_xor_sync(0xffffffffu, m0l, 2));
            m1l = fmaxf(m1l, __shfl_xor_sync(0xffffffffu, m1l, 1));
            m1l = fmaxf(m1l, __shfl_xor_sync(0xffffffffu, m1l, 2));
            const float m0n = fmaxf(m0, m0l), m1n = fmaxf(m1, m1l);
            const float a0 = ex2((m0 - m0n) * SL2E);
            const float a1 = ex2((m1 - m1n) * SL2E);
            m0 = m0n; m1 = m1n;

            float sum0 = 0.f, sum1 = 0.f;
#pragma unroll
            for (int nf = 0; nf < 8; nf++) {
                s[nf][0] = ex2((s[nf][0] - m0n) * SL2E); sum0 += s[nf][0];
                s[nf][1] = ex2((s[nf][1] - m0n) * SL2E); sum0 += s[nf][1];
                s[nf][2] = ex2((s[nf][2] - m1n) * SL2E); sum1 += s[nf][2];
                s[nf][3] = ex2((s[nf][3] - m1n) * SL2E); sum1 += s[nf][3];
            }
            sum0 += __shfl_xor_sync(0xffffffffu, sum0, 1);
            sum0 += __shfl_xor_sync(0xffffffffu, sum0, 2);
            sum1 += __shfl_xor_sync(0xffffffffu, sum1, 1);
            sum1 += __shfl_xor_sync(0xffffffffu, sum1, 2);
            l0 = l0 * a0 + sum0;
            l1 = l1 * a1 + sum1;

#pragma unroll
            for (int nf = 0; nf < 16; nf++) {
                o[nf][0] *= a0; o[nf][1] *= a0;
                o[nf][2] *= a1; o[nf][3] *= a1;
            }

            // ---- O += P V : P single fp16, V hi/lo (2 chains) ----
            const uint32_t vb = kb + 2 * FL_TILE;
#pragma unroll
            for (int kf2 = 0; kf2 < 4; kf2++) {
                uint32_t ah[4];
#pragma unroll
                for (int q2 = 0; q2 < 2; q2++) {
                    const float* sp = s[2 * kf2 + q2];
                    ah[q2 * 2 + 0] = pack_f16x2(sp[0], sp[1]);
                    ah[q2 * 2 + 1] = pack_f16x2(sp[2], sp[3]);
                }
#pragma unroll
                for (int nfp = 0; nfp < 8; nfp++) {
                    uint32_t vh4[4], vl4[4];
                    const uint32_t va = vb + (kf2 * 16 + vrow) * FL_ROWB + vcolb + nfp * 32;
                    ldsm4t(vh4, va);
                    ldsm4t(vl4, va + FL_TILE);
                    mma_f16(o[2 * nfp], ah, vh4);
                    mma_f16(o[2 * nfp], ah, vl4);
                    mma_f16(o[2 * nfp + 1], ah, vh4 + 2);
                    mma_f16(o[2 * nfp + 1], ah, vl4 + 2);
                }
            }
        }
    }

    // ---- finalize: write fp16 single (A operand of WO GEMM) ----
    const float il0 = 1.f / l0, il1 = 1.f / l1;
    const size_t yb = hb + (size_t)r0g * EMB + (lane & 3) * 2;
#pragma unroll
    for (int nf = 0; nf < 16; nf++) {
        *(uint32_t*)(Y + yb + nf * 8) =
            pack_f16x2(o[nf][0] * il0, o[nf][1] * il0);
        *(uint32_t*)(Y + yb + (size_t)8 * EMB + nf * 8) =
            pack_f16x2(o[nf][2] * il1, o[nf][3] * il1);
    }
}

// =====================================================================
// launch
// =====================================================================
extern "C" void kernel_launch(void* const* d_in, const int* in_sizes, int n_in,
                              void* d_out, int out_size)
{
    const float* x  = (const float*)d_in[0];
    const float* wq = (const float*)d_in[1];
    const float* wk = (const float*)d_in[2];
    const float* wv = (const float*)d_in[3];
    const float* wo = (const float*)d_in[4];
    float* out = (float*)d_out;

    float *gq, *gk, *ct, *st;
    __half *ga, *wthi, *wtlo, *qh, *ql, *kh, *kl, *vh, *vl;
    cudaGetSymbolAddress((void**)&gq, g_q);
    cudaGetSymbolAddress((void**)&gk, g_k);
    cudaGetSymbolAddress((void**)&ct, g_cos);
    cudaGetSymbolAddress((void**)&st, g_sin);
    cudaGetSymbolAddress((void**)&ga, g_a);
    cudaGetSymbolAddress((void**)&wthi, g_wthi);
    cudaGetSymbolAddress((void**)&wtlo, g_wtlo);
    cudaGetSymbolAddress((void**)&qh, g_qh);
    cudaGetSymbolAddress((void**)&ql, g_ql);
    cudaGetSymbolAddress((void**)&kh, g_kh);
    cudaGetSymbolAddress((void**)&kl, g_kl);
    cudaGetSymbolAddress((void**)&vh, g_vh);
    cudaGetSymbolAddress((void**)&vl, g_vl);

    cudaFuncSetAttribute(mma_gemm_kernel,
                         cudaFuncAttributeMaxDynamicSharedMemorySize, GEMM_SMEM);
    cudaFuncSetAttribute(flash_mma_kernel,
                         cudaFuncAttributeMaxDynamicSharedMemorySize, FL_SMEM);

    const int n4 = (int)(ELEMS / 4);
    const dim3 sgrid((n4 + 255) / 256);
    const size_t WSZ = (size_t)EMB * EMB;

    // prep: rope tables, x -> fp16, all 4 weights (x64, hi/lo) in one launch
    rope_table_kernel<<<(SEQ * 64 + 255) / 256, 256>>>(ct, st);
    conv16_kernel<<<sgrid, 256>>>(x, ga, n4);
    dim3 wgrid(EMB / 32, EMB / 32, 4);
    wsplit4_kernel<<<wgrid, 256>>>(wq, wk, wv, wo, wthi, wtlo);

    // fused QKV GEMM: q,k fp32; v directly fp16 hi/lo
    dim3 qkvgrid(3 * EMB / BN, MROWS / BM);   // (24, 64)
    mma_gemm_kernel<<<qkvgrid, 256, GEMM_SMEM>>>(
        ga, wthi, wtlo, EMB, 1, gq, gk, vh, vl);

    // RoPE + RMSNorm + fp16 split, Q and K together (no scale)
    ropeprep2_kernel<<<2 * BATCH * SEQ * NHEAD / 8, 256>>>(
        gq, gk, ct, st, qh, ql, kh, kl);

    // flash attention -> writes ga (fp16 single) directly
    dim3 fgrid(SEQ / 128, NHEAD, BATCH);
    flash_mma_kernel<<<fgrid, 256, FL_SMEM>>>(qh, ql, kh, kl, vh, vl, ga);

    // out = y @ wo
    dim3 ogrid(EMB / BN, MROWS / BM);
    mma_gemm_kernel<<<ogrid, 256, GEMM_SMEM>>>(
        ga, wthi + 3 * WSZ, wtlo + 3 * WSZ, EMB, 0,
        out, nullptr, nullptr, nullptr);
}

// round 14
// speedup vs baseline: 1.5108x; 1.0958x over previous
#include <cuda_runtime.h>
#include <cuda_bf16.h>
#include <cuda_fp16.h>
#include <math.h>
#include <stdint.h>

// ---------------- constants ----------------
#define BATCH 4
#define SEQ   2048
#define EMB   2048
#define NHEAD 16
#define HDIM  128
#define MROWS (BATCH*SEQ)               // 8192
#define ELEMS ((size_t)BATCH*SEQ*EMB)   // 16777216
#define RMS_EPS 1.1920929e-07f
// softmax: exp(s*scale) = exp2(s * SL2E), SL2E = (1/sqrt(128))*log2(e)
#define SL2E 0.1275290959651556f
#define WSCALE 64.0f
#define WINV   0.015625f

// ---------------- scratch (device globals: allocation-free) ----------------
__device__ float g_q[ELEMS];
__device__ float g_k[ELEMS];
__device__ __half g_a[ELEMS];                      // fp16 A operand (x, then Y)
__device__ __half g_wthi[(size_t)4*EMB*EMB];       // transposed weights (x64) hi
__device__ __half g_wtlo[(size_t)4*EMB*EMB];       // lo
__device__ __half g_qh[ELEMS];
__device__ __half g_ql[ELEMS];
__device__ __half g_kh[ELEMS];                     // K single fp16
__device__ __half g_vh[ELEMS];                     // V single fp16
__device__ float g_cos[SEQ*64];
__device__ float g_sin[SEQ*64];

// =====================================================================
// PTX helpers (standard sm_80+ instructions; valid on plain sm_103)
// =====================================================================
__device__ __forceinline__ uint32_t smem_to_u32(const void* p) {
    uint32_t a;
    asm("{ .reg .u64 t; cvta.to.shared.u64 t, %1; cvt.u32.u64 %0, t; }"
        : "=r"(a) : "l"(p));
    return a;
}

__device__ __forceinline__ void ldsm4(uint32_t* r, uint32_t addr) {
    asm volatile("ldmatrix.sync.aligned.m8n8.x4.shared.b16 {%0,%1,%2,%3}, [%4];"
        : "=r"(r[0]), "=r"(r[1]), "=r"(r[2]), "=r"(r[3]) : "r"(addr));
}
__device__ __forceinline__ void ldsm4t(uint32_t* r, uint32_t addr) {
    asm volatile("ldmatrix.sync.aligned.m8n8.x4.trans.shared.b16 {%0,%1,%2,%3}, [%4];"
        : "=r"(r[0]), "=r"(r[1]), "=r"(r[2]), "=r"(r[3]) : "r"(addr));
}

__device__ __forceinline__ void mma_f16(float* c, const uint32_t* a, const uint32_t* b) {
    asm volatile(
        "mma.sync.aligned.m16n8k16.row.col.f32.f16.f16.f32 "
        "{%0,%1,%2,%3}, {%4,%5,%6,%7}, {%8,%9}, {%0,%1,%2,%3};"
        : "+f"(c[0]), "+f"(c[1]), "+f"(c[2]), "+f"(c[3])
        : "r"(a[0]), "r"(a[1]), "r"(a[2]), "r"(a[3]), "r"(b[0]), "r"(b[1]));
}

__device__ __forceinline__ uint32_t pack_f16x2(float lo, float hi) {
    __half2 h = __floats2half2_rn(lo, hi);
    return *(uint32_t*)&h;
}

// fast exp2 (single SASS MUFU.EX2)
__device__ __forceinline__ float ex2(float x) {
    float y;
    asm("ex2.approx.f32 %0, %1;" : "=f"(y) : "f"(x));
    return y;
}

#define CP_ASYNC16(dst, src) \
    asm volatile("cp.async.cg.shared.global [%0], [%1], 16;" :: "r"(dst), "l"(src) : "memory")
#define CP_COMMIT() asm volatile("cp.async.commit_group;" ::: "memory")
#define CP_WAIT0()  asm volatile("cp.async.wait_group 0;" ::: "memory")

// =====================================================================
// conv16: fp32 -> fp16 (single)
// =====================================================================
__global__ __launch_bounds__(256) void conv16_kernel(
    const float* __restrict__ in, __half* __restrict__ out, int n4)
{
    int i = blockIdx.x * 256 + threadIdx.x;
    if (i >= n4) return;
    float4 v = ((const float4*)in)[i];
    uint2 o;
    o.x = pack_f16x2(v.x, v.y);
    o.y = pack_f16x2(v.z, v.w);
    ((uint2*)out)[i] = o;
}

// =====================================================================
// 4 weights: transpose + x64 scale + fp16 hi/lo split
// =====================================================================
__global__ __launch_bounds__(256) void wsplit4_kernel(
    const float* __restrict__ w0, const float* __restrict__ w1,
    const float* __restrict__ w2, const float* __restrict__ w3,
    __half* __restrict__ hi_base, __half* __restrict__ lo_base)
{
    __shared__ float tile[32][33];
    const int z = blockIdx.z;
    const float* w = (z == 0) ? w0 : (z == 1) ? w1 : (z == 2) ? w2 : w3;
    __half* hi = hi_base + (size_t)z * EMB * EMB;
    __half* lo = lo_base + (size_t)z * EMB * EMB;

    int n0 = blockIdx.x * 32, k0 = blockIdx.y * 32;
    int tx = threadIdx.x & 31, ty = threadIdx.x >> 5;
#pragma unroll
    for (int i = 0; i < 32; i += 8)
        tile[ty + i][tx] = w[(size_t)(k0 + ty + i) * EMB + n0 + tx];
    __syncthreads();
#pragma unroll
    for (int i = 0; i < 32; i += 8) {
        float v = tile[tx][ty + i] * WSCALE;
        __half h = __float2half_rn(v);
        size_t o = (size_t)(n0 + ty + i) * EMB + k0 + tx;
        hi[o] = h;
        lo[o] = __float2half_rn(v - __half2float(h));
    }
}

// =====================================================================
// RoPE table precompute (double precision, once)
// =====================================================================
__global__ __launch_bounds__(256) void rope_table_kernel(
    float* __restrict__ ct, float* __restrict__ st)
{
    const int idx = blockIdx.x * 256 + threadIdx.x;
    if (idx >= SEQ * 64) return;
    const int tp = idx >> 6, i = idx & 63;
    double inv = exp(-((double)i / 64.0) * log(10000.0));
    double ang = (double)tp * inv;
    double sd, cd;
    sincos(ang, &sd, &cd);
    ct[idx] = (float)cd;
    st[idx] = (float)sd;
}

// =====================================================================
// mma.sync GEMM: C = (A * B^T)/64.  A single fp16; B fp16 hi/lo (x64).
// 2 chains: A*Bhi + A*Blo.  2-stage cp.async, ONE sync per k-iter.
// Block tile 128x256x64, 8 warps (2 x 4), warp tile 64x64.
// mode 0: fp32 -> c0.  mode 1 (QKV fused, N=6144): q,k fp32; V fp16 single.
// =====================================================================
#define BM 128
#define BN 256
#define BK 64
#define RSTRB 144
#define TA (128 * RSTRB)          // 18432 (A: one tile)
#define TB (256 * RSTRB)          // 36864
#define STG_B (TA + 2*TB)         // 92160
#define GEMM_SMEM (2 * STG_B)     // 184320

__global__ __launch_bounds__(256) void mma_gemm_kernel(
    const __half* __restrict__ A,
    const __half* __restrict__ Bhi, const __half* __restrict__ Blo,
    int K, int mode,
    float* __restrict__ c0, float* __restrict__ c1,
    __half* __restrict__ c2)
{
    extern __shared__ char smc[];
    const uint32_t sb = smem_to_u32(smc);
    const int t = threadIdx.x;
    const int lane = t & 31;
    const int wid = t >> 5;
    const int warp_m = wid & 1;
    const int warp_n = wid >> 1;
    const int row0 = blockIdx.y * BM;
    const int col0 = blockIdx.x * BN;

    float acc[4][8][4];
#pragma unroll
    for (int i = 0; i < 4; i++)
#pragma unroll
        for (int j = 0; j < 8; j++)
#pragma unroll
            for (int r = 0; r < 4; r++) acc[i][j][r] = 0.f;

    auto load_stage = [&](int s, int k0) {
        const uint32_t base = sb + s * STG_B;
#pragma unroll
        for (int i = 0; i < 4; i++) {
            const int idx = t + i * 256;
            const int r = idx >> 3, c = idx & 7;
            CP_ASYNC16(base + r * RSTRB + c * 16,
                       A + (size_t)(row0 + r) * K + k0 + c * 8);
        }
#pragma unroll
        for (int i = 0; i < 8; i++) {
            const int idx = t + i * 256;
            const int r = idx >> 3, c = idx & 7;
            const size_t g = (size_t)(col0 + r) * K + k0 + c * 8;
            const uint32_t d = base + TA + r * RSTRB + c * 16;
            CP_ASYNC16(d, Bhi + g);
            CP_ASYNC16(d + TB, Blo + g);
        }
    };

    const int nIter = K / BK;
    load_stage(0, 0);
    CP_COMMIT();

    for (int it = 0; it < nIter; it++) {
        CP_WAIT0();
        __syncthreads();
        if (it + 1 < nIter) {
            load_stage((it + 1) & 1, (it + 1) * BK);
            CP_COMMIT();
        }

        const uint32_t abase = sb + (it & 1) * STG_B;
        const uint32_t bbase = abase + TA;
        const int arow = warp_m * 64 + (lane & 15);
        const int brow = warp_n * 64 + ((lane >> 4) << 3) + (lane & 7);

#pragma unroll
        for (int ks = 0; ks < 4; ks++) {
            uint32_t ah[4][4], bh[4][4], bl[4][4];
            const uint32_t acol = ks * 32 + ((lane >> 4) << 4);
            const uint32_t bcol = ks * 32 + (((lane >> 3) & 1) << 4);
#pragma unroll
            for (int mf = 0; mf < 4; mf++)
                ldsm4(ah[mf], abase + (arow + mf * 16) * RSTRB + acol);
#pragma unroll
            for (int bf = 0; bf < 4; bf++) {
                const uint32_t bd = bbase + (brow + bf * 16) * RSTRB + bcol;
                ldsm4(bh[bf], bd);
                ldsm4(bl[bf], bd + TB);
            }
#pragma unroll
            for (int mf = 0; mf < 4; mf++) {
#pragma unroll
                for (int nf = 0; nf < 8; nf++) {
                    const uint32_t* bhp = &bh[nf >> 1][(nf & 1) * 2];
                    const uint32_t* blp = &bl[nf >> 1][(nf & 1) * 2];
                    mma_f16(acc[mf][nf], ah[mf], bhp);
                    mma_f16(acc[mf][nf], ah[mf], blp);
                }
            }
        }
    }

    // ---- epilogue (unscale by 1/64) ----
    const int mbase = row0 + warp_m * 64 + (lane >> 2);
    const int nb = col0 + warp_n * 64 + (lane & 3) * 2;
#pragma unroll
    for (int mf = 0; mf < 4; mf++) {
#pragma unroll
        for (int nf = 0; nf < 8; nf++) {
            const int n = nb + nf * 8;
            const int m0 = mbase + mf * 16;
            float a0 = acc[mf][nf][0] * WINV, a1 = acc[mf][nf][1] * WINV;
            float a2 = acc[mf][nf][2] * WINV, a3 = acc[mf][nf][3] * WINV;
            if (mode == 0) {
                const size_t o0 = (size_t)m0 * EMB + n;
                *(float2*)(c0 + o0) = make_float2(a0, a1);
                *(float2*)(c0 + o0 + 8 * EMB) = make_float2(a2, a3);
            } else {
                const int which = n >> 11;
                const int nloc = n & 2047;
                const size_t o0 = (size_t)m0 * EMB + nloc;
                if (which == 0) {
                    *(float2*)(c0 + o0) = make_float2(a0, a1);
                    *(float2*)(c0 + o0 + 8 * EMB) = make_float2(a2, a3);
                } else if (which == 1) {
                    *(float2*)(c1 + o0) = make_float2(a0, a1);
                    *(float2*)(c1 + o0 + 8 * EMB) = make_float2(a2, a3);
                } else {
                    *(uint32_t*)(c2 + o0) = pack_f16x2(a0, a1);
                    *(uint32_t*)(c2 + o0 + 8 * EMB) = pack_f16x2(a2, a3);
                }
            }
        }
    }
}

// =====================================================================
// RoPE + RMSNorm: Q -> fp16 hi/lo, K -> fp16 single.
// One WARP per (buffer, b, t, h) head-row; Q and K in one launch.
// =====================================================================
__global__ __launch_bounds__(256) void ropeprep2_kernel(
    const float* __restrict__ q, const float* __restrict__ k,
    const float* __restrict__ ct, const float* __restrict__ st,
    __half* __restrict__ qh, __half* __restrict__ ql,
    __half* __restrict__ kh)
{
    const int w = blockIdx.x * 8 + (threadIdx.x >> 5);
    const int lane = threadIdx.x & 31;
    const int sel = w >> 17;            // 0=Q, 1=K
    const int w2 = w & 131071;
    const int b = w2 >> 15;
    const int r = w2 & 32767;
    const int tp = r >> 4;
    const int h = r & 15;

    const float* buf = sel ? k : q;
    const size_t base = ((size_t)b * SEQ + tp) * EMB + (size_t)h * HDIM;

    const float x1a = buf[base + lane];
    const float x1b = buf[base + 32 + lane];
    const float x2a = buf[base + 64 + lane];
    const float x2b = buf[base + 96 + lane];
    const float ca = ct[tp * 64 + lane],      sa  = st[tp * 64 + lane];
    const float cb = ct[tp * 64 + 32 + lane], sb2 = st[tp * 64 + 32 + lane];

    const float n1a = x1a * ca - x2a * sa;
    const float n2a = x1a * sa + x2a * ca;
    const float n1b = x1b * cb - x2b * sb2;
    const float n2b = x1b * sb2 + x2b * cb;

    float sq = n1a * n1a + n2a * n2a + n1b * n1b + n2b * n2b;
#pragma unroll
    for (int o = 16; o > 0; o >>= 1)
        sq += __shfl_xor_sync(0xffffffffu, sq, o);

    const float rs = rsqrtf(sq * (1.0f / 128.0f) + RMS_EPS);

    const float y0 = n1a * rs, y1 = n1b * rs, y2 = n2a * rs, y3 = n2b * rs;
    if (sel) {
        kh[base + lane]      = __float2half_rn(y0);
        kh[base + 32 + lane] = __float2half_rn(y1);
        kh[base + 64 + lane] = __float2half_rn(y2);
        kh[base + 96 + lane] = __float2half_rn(y3);
    } else {
        __half h0 = __float2half_rn(y0);
        __half h1 = __float2half_rn(y1);
        __half h2 = __float2half_rn(y2);
        __half h3 = __float2half_rn(y3);
        qh[base + lane]      = h0;
        qh[base + 32 + lane] = h1;
        qh[base + 64 + lane] = h2;
        qh[base + 96 + lane] = h3;
        ql[base + lane]      = __float2half_rn(y0 - __half2float(h0));
        ql[base + 32 + lane] = __float2half_rn(y1 - __half2float(h1));
        ql[base + 64 + lane] = __float2half_rn(y2 - __half2float(h2));
        ql[base + 96 + lane] = __float2half_rn(y3 - __half2float(h3));
    }
}

// =====================================================================
// Flash attention, fp16 mma: S = 2 chains (Qh·K + Ql·K, K single),
// P·V = 1 chain (P,V single). Q fragments in registers.
// smem: [0, 4*FL_TILE) = Q hi + Q lo; then 2 KV stages (K tile + V tile).
// =====================================================================
#define FL_STR  136
#define FL_ROWB (FL_STR*2)
#define FL_TILE (64*FL_ROWB)            // 17408
#define FL_STG  (2*FL_TILE)             // K + V tiles = 34816 B
#define FL_QLO  (128*FL_ROWB)           // 34816 (Q lo offset)
#define FL_KV0  (4*FL_TILE)             // 69632 (first KV stage — after Q hi+lo!)
#define FL_SMEM (4*FL_TILE + 2*FL_STG)  // 139264 B

__global__ __launch_bounds__(256, 1) void flash_mma_kernel(
    const __half* __restrict__ Qh, const __half* __restrict__ Ql,
    const __half* __restrict__ Kh, const __half* __restrict__ Vh,
    __half* __restrict__ Y)
{
    extern __shared__ char smc[];
    const uint32_t sb = smem_to_u32(smc);
    const int t = threadIdx.x;
    const int lane = t & 31;
    const int w = t >> 5;
    const int qi = gridDim.x - 1 - blockIdx.x;
    const int h = blockIdx.y, b = blockIdx.z;
    const int qs = qi * 128;
    const size_t hb = ((size_t)b * SEQ) * EMB + (size_t)h * HDIM;

#pragma unroll
    for (int i = 0; i < 8; i++) {
        const int idx = t + i * 256;
        const int r = idx >> 4, c = idx & 15;
        const size_t g = hb + (size_t)(qs + r) * EMB + c * 8;
        CP_ASYNC16(sb + r * FL_ROWB + c * 16, Qh + g);
        CP_ASYNC16(sb + FL_QLO + r * FL_ROWB + c * 16, Ql + g);
    }
    CP_COMMIT();

    auto load_kv = [&](int s, int ks) {
        const uint32_t base = sb + FL_KV0 + s * FL_STG;
#pragma unroll
        for (int i = 0; i < 4; i++) {
            const int idx = t + i * 256;
            const int r = idx >> 4, c = idx & 15;
            const size_t g = hb + (size_t)(ks + r) * EMB + c * 8;
            CP_ASYNC16(base + r * FL_ROWB + c * 16, Kh + g);
            CP_ASYNC16(base + FL_TILE + r * FL_ROWB + c * 16, Vh + g);
        }
    };

    load_kv(0, 0);
    CP_COMMIT();

    float m0 = -INFINITY, m1 = -INFINITY, l0 = 0.f, l1 = 0.f;
    float o[16][4];
#pragma unroll
    for (int i = 0; i < 16; i++)
#pragma unroll
        for (int j = 0; j < 4; j++) o[i][j] = 0.f;

    const uint32_t q_addr = sb + (w * 16 + (lane & 15)) * FL_ROWB + (lane >> 4) * 16;
    const int krow = (lane & 7) + ((lane >> 4) << 3);
    const uint32_t kcolb = ((lane >> 3) & 1) * 16;
    const int vrow = (lane & 7) + (((lane >> 3) & 1) << 3);
    const uint32_t vcolb = (lane >> 4) * 16;

    const int r0g = qs + w * 16 + (lane >> 2);
    const int r1g = r0g + 8;
    const int nkt = (qs + 128) / 64;

    // ---- preload Q fragments into registers ----
    CP_WAIT0();
    __syncthreads();
    uint32_t qa_r[8][4], qla_r[8][4];
#pragma unroll
    for (int kf = 0; kf < 8; kf++) {
        ldsm4(qa_r[kf], q_addr + kf * 32);
        ldsm4(qla_r[kf], q_addr + FL_QLO + kf * 32);
    }

    for (int jt = 0; jt < nkt; jt++) {
        CP_WAIT0();
        __syncthreads();
        if (jt + 1 < nkt) { load_kv((jt + 1) & 1, (jt + 1) * 64); CP_COMMIT(); }

        const int ks = jt * 64;
        if (ks <= qs + w * 16 + 15) {
            const uint32_t kb = sb + FL_KV0 + (jt & 1) * FL_STG;

            float s[8][4];
#pragma unroll
            for (int i = 0; i < 8; i++)
#pragma unroll
                for (int j = 0; j < 4; j++) s[i][j] = 0.f;

#pragma unroll
            for (int kf = 0; kf < 8; kf++) {
#pragma unroll
                for (int nfp = 0; nfp < 4; nfp++) {
                    uint32_t kh4[4];
                    ldsm4(kh4, kb + (nfp * 16 + krow) * FL_ROWB + kcolb + kf * 32);
                    mma_f16(s[2 * nfp], qa_r[kf], kh4);
                    mma_f16(s[2 * nfp], qla_r[kf], kh4);
                    mma_f16(s[2 * nfp + 1], qa_r[kf], kh4 + 2);
                    mma_f16(s[2 * nfp + 1], qla_r[kf], kh4 + 2);
                }
            }

            if (ks + 63 > r0g) {
#pragma unroll
                for (int nf = 0; nf < 8; nf++) {
                    const int kc = ks + nf * 8 + (lane & 3) * 2;
                    if (kc > r0g)     s[nf][0] = -1e30f;
                    if (kc + 1 > r0g) s[nf][1] = -1e30f;
                    if (kc > r1g)     s[nf][2] = -1e30f;
                    if (kc + 1 > r1g) s[nf][3] = -1e30f;
                }
            }

            float m0l = -INFINITY, m1l = -INFINITY;
#pragma unroll
            for (int nf = 0; nf < 8; nf++) {
                m0l = fmaxf(m0l, fmaxf(s[nf][0], s[nf][1]));
                m1l = fmaxf(m1l, fmaxf(s[nf][2], s[nf][3]));
            }
            m0l = fmaxf(m0l, __shfl_xor_sync(0xffffffffu, m0l, 1));
            m0l = fmaxf(m0l, __shfl_xor_sync(0xffffffffu, m0l, 2));
            m1l = fmaxf(m1l, __shfl_xor_sync(0xffffffffu, m1l, 1));
            m1l = fmaxf(m1l, __shfl_xor_sync(0xffffffffu, m1l, 2));
            const float m0n = fmaxf(m0, m0l), m1n = fmaxf(m1, m1l);
            const float a0 = ex2((m0 - m0n) * SL2E);
            const float a1 = ex2((m1 - m1n) * SL2E);
            m0 = m0n; m1 = m1n;

            float sum0 = 0.f, sum1 = 0.f;
#pragma unroll
            for (int nf = 0; nf < 8; nf++) {
                s[nf][0] = ex2((s[nf][0] - m0n) * SL2E); sum0 += s[nf][0];
                s[nf][1] = ex2((s[nf][1] - m0n) * SL2E); sum0 += s[nf][1];
                s[nf][2] = ex2((s[nf][2] - m1n) * SL2E); sum1 += s[nf][2];
                s[nf][3] = ex2((s[nf][3] - m1n) * SL2E); sum1 += s[nf][3];
            }
            sum0 += __shfl_xor_sync(0xffffffffu, sum0, 1);
            sum0 += __shfl_xor_sync(0xffffffffu, sum0, 2);
            sum1 += __shfl_xor_sync(0xffffffffu, sum1, 1);
            sum1 += __shfl_xor_sync(0xffffffffu, sum1, 2);
            l0 = l0 * a0 + sum0;
            l1 = l1 * a1 + sum1;

#pragma unroll
            for (int nf = 0; nf < 16; nf++) {
                o[nf][0] *= a0; o[nf][1] *= a0;
                o[nf][2] *= a1; o[nf][3] *= a1;
            }

            // ---- O += P V : single chain ----
            const uint32_t vb = kb + FL_TILE;
#pragma unroll
            for (int kf2 = 0; kf2 < 4; kf2++) {
                uint32_t ah[4];
#pragma unroll
                for (int q2 = 0; q2 < 2; q2++) {
                    const float* sp = s[2 * kf2 + q2];
                    ah[q2 * 2 + 0] = pack_f16x2(sp[0], sp[1]);
                    ah[q2 * 2 + 1] = pack_f16x2(sp[2], sp[3]);
                }
#pragma unroll
                for (int nfp = 0; nfp < 8; nfp++) {
                    uint32_t vh4[4];
                    ldsm4t(vh4, vb + (kf2 * 16 + vrow) * FL_ROWB + vcolb + nfp * 32);
                    mma_f16(o[2 * nfp], ah, vh4);
                    mma_f16(o[2 * nfp + 1], ah, vh4 + 2);
                }
            }
        }
    }

    // ---- finalize: write fp16 single (A operand of WO GEMM) ----
    const float il0 = 1.f / l0, il1 = 1.f / l1;
    const size_t yb = hb + (size_t)r0g * EMB + (lane & 3) * 2;
#pragma unroll
    for (int nf = 0; nf < 16; nf++) {
        *(uint32_t*)(Y + yb + nf * 8) =
            pack_f16x2(o[nf][0] * il0, o[nf][1] * il0);
        *(uint32_t*)(Y + yb + (size_t)8 * EMB + nf * 8) =
            pack_f16x2(o[nf][2] * il1, o[nf][3] * il1);
    }
}

// =====================================================================
// launch
// =====================================================================
extern "C" void kernel_launch(void* const* d_in, const int* in_sizes, int n_in,
                              void* d_out, int out_size)
{
    const float* x  = (const float*)d_in[0];
    const float* wq = (const float*)d_in[1];
    const float* wk = (const float*)d_in[2];
    const float* wv = (const float*)d_in[3];
    const float* wo = (const float*)d_in[4];
    float* out = (float*)d_out;

    float *gq, *gk, *ct, *st;
    __half *ga, *wthi, *wtlo, *qh, *ql, *kh, *vh;
    cudaGetSymbolAddress((void**)&gq, g_q);
    cudaGetSymbolAddress((void**)&gk, g_k);
    cudaGetSymbolAddress((void**)&ct, g_cos);
    cudaGetSymbolAddress((void**)&st, g_sin);
    cudaGetSymbolAddress((void**)&ga, g_a);
    cudaGetSymbolAddress((void**)&wthi, g_wthi);
    cudaGetSymbolAddress((void**)&wtlo, g_wtlo);
    cudaGetSymbolAddress((void**)&qh, g_qh);
    cudaGetSymbolAddress((void**)&ql, g_ql);
    cudaGetSymbolAddress((void**)&kh, g_kh);
    cudaGetSymbolAddress((void**)&vh, g_vh);

    cudaFuncSetAttribute(mma_gemm_kernel,
                         cudaFuncAttributeMaxDynamicSharedMemorySize, GEMM_SMEM);
    cudaFuncSetAttribute(flash_mma_kernel,
                         cudaFuncAttributeMaxDynamicSharedMemorySize, FL_SMEM);

    const int n4 = (int)(ELEMS / 4);
    const dim3 sgrid((n4 + 255) / 256);
    const size_t WSZ = (size_t)EMB * EMB;

    // prep: rope tables, x -> fp16, all 4 weights (x64, hi/lo) in one launch
    rope_table_kernel<<<(SEQ * 64 + 255) / 256, 256>>>(ct, st);
    conv16_kernel<<<sgrid, 256>>>(x, ga, n4);
    dim3 wgrid(EMB / 32, EMB / 32, 4);
    wsplit4_kernel<<<wgrid, 256>>>(wq, wk, wv, wo, wthi, wtlo);

    // fused QKV GEMM: q,k fp32; v directly fp16 single
    dim3 qkvgrid(3 * EMB / BN, MROWS / BM);   // (24, 64)
    mma_gemm_kernel<<<qkvgrid, 256, GEMM_SMEM>>>(
        ga, wthi, wtlo, EMB, 1, gq, gk, vh);

    // RoPE + RMSNorm: Q -> hi/lo, K -> single
    ropeprep2_kernel<<<2 * BATCH * SEQ * NHEAD / 8, 256>>>(
        gq, gk, ct, st, qh, ql, kh);

    // flash attention -> writes ga (fp16 single) directly
    dim3 fgrid(SEQ / 128, NHEAD, BATCH);
    flash_mma_kernel<<<fgrid, 256, FL_SMEM>>>(qh, ql, kh, vh, ga);

    // out = y @ wo
    dim3 ogrid(EMB / BN, MROWS / BM);
    mma_gemm_kernel<<<ogrid, 256, GEMM_SMEM>>>(
        ga, wthi + 3 * WSZ, wtlo + 3 * WSZ, EMB, 0,
        out, nullptr, nullptr);
}